// round 4
// baseline (speedup 1.0000x reference)
#include <cuda_runtime.h>

// ---------------------------------------------------------------------------
// NeuralAdditiveModel: out[b] = bias + sum_f MLP_f(x[b,f])
//   MLP_f: 1 -> H1(128) relu -> H2(64) relu -> H3(32) relu -> 1
// Strategy: fp32 SIMT with packed f32x2 FMA (sm_103a FFMA2), one CTA per
// (feature-group, batch-tile), weights staged in SMEM, row fully in regs.
// Deterministic 2-stage reduction through a __device__ scratch buffer.
// ---------------------------------------------------------------------------

#define B_TOTAL 8192
#define F_TOTAL 256
#define H1 128
#define H2 64
#define H3 32

#define FGROUPS 8
#define FEATS_PER_GROUP (F_TOTAL / FGROUPS)      // 32
#define ROWS_PER_BLOCK 128
#define BTILES (B_TOTAL / ROWS_PER_BLOCK)        // 64

__device__ float g_partial[FGROUPS * B_TOTAL];

// ---- packed f32x2 helpers --------------------------------------------------
__device__ __forceinline__ unsigned long long pack2(float lo, float hi) {
    unsigned long long r;
    asm("mov.b64 %0, {%1, %2};" : "=l"(r) : "f"(lo), "f"(hi));
    return r;
}
__device__ __forceinline__ void unpack2(unsigned long long v, float& lo, float& hi) {
    asm("mov.b64 {%0, %1}, %2;" : "=f"(lo), "=f"(hi) : "l"(v));
}
// d = a * b + d   (two independent fp32 FMAs, bit-identical to scalar fmaf)
__device__ __forceinline__ void ffma2(unsigned long long& d,
                                      unsigned long long a,
                                      unsigned long long b) {
    asm("fma.rn.f32x2 %0, %1, %2, %0;" : "+l"(d) : "l"(a), "l"(b));
}

// ---------------------------------------------------------------------------
__global__ __launch_bounds__(ROWS_PER_BLOCK)
void nam_main_kernel(const float* __restrict__ x,
                     const float* __restrict__ W1, const float* __restrict__ b1,
                     const float* __restrict__ W2, const float* __restrict__ b2,
                     const float* __restrict__ W3, const float* __restrict__ b3,
                     const float* __restrict__ W4, const float* __restrict__ b4)
{
    __shared__ __align__(16) float sW2[H1 * H2];   // 32 KB
    __shared__ __align__(16) float sW3[H2 * H3];   //  8 KB
    __shared__ __align__(16) float sW1[H1];
    __shared__ __align__(16) float sb1[H1];
    __shared__ __align__(16) float sb2[H2];
    __shared__ __align__(16) float sb3[H3];
    __shared__ __align__(16) float sW4[H3];
    __shared__ float sb4;

    const int tid = threadIdx.x;
    const int row = blockIdx.x * ROWS_PER_BLOCK + tid;   // batch row
    const int f0  = blockIdx.y * FEATS_PER_GROUP;

    float acc_out = 0.0f;

    for (int fi = 0; fi < FEATS_PER_GROUP; ++fi) {
        const int f = f0 + fi;

        // ---- cooperative weight staging (vectorized, broadcast-friendly) ----
        {
            const float4* s2 = (const float4*)(W2 + (size_t)f * (H1 * H2));
            float4* d2 = (float4*)sW2;
            #pragma unroll 4
            for (int i = tid; i < (H1 * H2) / 4; i += ROWS_PER_BLOCK) d2[i] = s2[i];

            const float4* s3 = (const float4*)(W3 + (size_t)f * (H2 * H3));
            float4* d3 = (float4*)sW3;
            #pragma unroll
            for (int i = tid; i < (H2 * H3) / 4; i += ROWS_PER_BLOCK) d3[i] = s3[i];

            if (tid < H1 / 4) {
                ((float4*)sW1)[tid] = ((const float4*)(W1 + (size_t)f * H1))[tid];
                ((float4*)sb1)[tid] = ((const float4*)(b1 + (size_t)f * H1))[tid];
            }
            if (tid >= 32 && tid < 32 + H2 / 4)
                ((float4*)sb2)[tid - 32] = ((const float4*)(b2 + (size_t)f * H2))[tid - 32];
            if (tid >= 48 && tid < 48 + H3 / 4)
                ((float4*)sb3)[tid - 48] = ((const float4*)(b3 + (size_t)f * H3))[tid - 48];
            if (tid >= 56 && tid < 56 + H3 / 4)
                ((float4*)sW4)[tid - 56] = ((const float4*)(W4 + (size_t)f * H3))[tid - 56];
            if (tid == 64) sb4 = b4[f];
        }
        __syncthreads();

        const float xv = x[(size_t)row * F_TOTAL + f];

        // ---- layer 1 + layer 2 fused: stream j, 32 packed z2 accumulators ----
        unsigned long long acc[H2 / 2];
        #pragma unroll
        for (int p = 0; p < H2 / 2; ++p)
            acc[p] = __double_as_longlong(((const double*)sb2)[p]);

        #pragma unroll 2
        for (int j = 0; j < H1; ++j) {
            float h = fmaxf(fmaf(xv, sW1[j], sb1[j]), 0.0f);
            const unsigned long long hp = pack2(h, h);
            const double2* wrow = (const double2*)(sW2 + j * H2);
            #pragma unroll
            for (int q = 0; q < H2 / 4; ++q) {   // 16 x LDS.128 -> 32 FFMA2
                double2 w = wrow[q];
                ffma2(acc[2 * q],     hp, __double_as_longlong(w.x));
                ffma2(acc[2 * q + 1], hp, __double_as_longlong(w.y));
            }
        }

        // ---- layer 3: 16 packed z3 accumulators (k-loop fully unrolled so
        //      acc[k/2] is a static register index) ----
        unsigned long long acc3[H3 / 2];
        #pragma unroll
        for (int p = 0; p < H3 / 2; ++p)
            acc3[p] = __double_as_longlong(((const double*)sb3)[p]);

        #pragma unroll
        for (int k = 0; k < H2; k += 2) {
            float lo, hi;
            unpack2(acc[k / 2], lo, hi);
            lo = fmaxf(lo, 0.0f);
            hi = fmaxf(hi, 0.0f);
            const unsigned long long hp0 = pack2(lo, lo);
            const unsigned long long hp1 = pack2(hi, hi);
            const double2* w0 = (const double2*)(sW3 + k * H3);
            const double2* w1 = (const double2*)(sW3 + (k + 1) * H3);
            #pragma unroll
            for (int q = 0; q < H3 / 4; ++q) {
                double2 a = w0[q];
                ffma2(acc3[2 * q],     hp0, __double_as_longlong(a.x));
                ffma2(acc3[2 * q + 1], hp0, __double_as_longlong(a.y));
            }
            #pragma unroll
            for (int q = 0; q < H3 / 4; ++q) {
                double2 a = w1[q];
                ffma2(acc3[2 * q],     hp1, __double_as_longlong(a.x));
                ffma2(acc3[2 * q + 1], hp1, __double_as_longlong(a.y));
            }
        }

        // ---- layer 4: relu(z3) . W4 + b4 ----
        float fout = sb4;
        #pragma unroll
        for (int m = 0; m < H3; m += 2) {
            float lo, hi;
            unpack2(acc3[m / 2], lo, hi);
            fout = fmaf(fmaxf(lo, 0.0f), sW4[m],     fout);
            fout = fmaf(fmaxf(hi, 0.0f), sW4[m + 1], fout);
        }
        acc_out += fout;

        __syncthreads();   // protect SMEM before next feature's staging
    }

    g_partial[blockIdx.y * B_TOTAL + row] = acc_out;
}

// ---------------------------------------------------------------------------
__global__ void nam_reduce_kernel(const float* __restrict__ bias,
                                  float* __restrict__ out)
{
    const int b = blockIdx.x * blockDim.x + threadIdx.x;
    if (b < B_TOTAL) {
        float s = bias[0];
        #pragma unroll
        for (int g = 0; g < FGROUPS; ++g)
            s += g_partial[g * B_TOTAL + b];
        out[b] = s;
    }
}

// ---------------------------------------------------------------------------
extern "C" void kernel_launch(void* const* d_in, const int* in_sizes, int n_in,
                              void* d_out, int out_size)
{
    (void)in_sizes; (void)n_in; (void)out_size;
    const float* x    = (const float*)d_in[0];
    const float* W1   = (const float*)d_in[1];
    const float* b1   = (const float*)d_in[2];
    const float* W2   = (const float*)d_in[3];
    const float* b2   = (const float*)d_in[4];
    const float* W3   = (const float*)d_in[5];
    const float* b3   = (const float*)d_in[6];
    const float* W4   = (const float*)d_in[7];
    const float* b4   = (const float*)d_in[8];
    const float* bias = (const float*)d_in[9];
    float* out = (float*)d_out;

    dim3 grid(BTILES, FGROUPS);
    nam_main_kernel<<<grid, ROWS_PER_BLOCK>>>(x, W1, b1, W2, b2, W3, b3, W4, b4);
    nam_reduce_kernel<<<(B_TOTAL + 255) / 256, 256>>>(bias, out);
}

// round 6
// speedup vs baseline: 2.5660x; 2.5660x over previous
#include <cuda_runtime.h>
#include <cuda_bf16.h>
#include <cstdint>

// ---------------------------------------------------------------------------
// NAM via warp-level mma.sync (bf16 3-pass split), fused per-feature pipeline.
// ---------------------------------------------------------------------------

#define B_TOTAL 8192
#define F_TOTAL 256
#define FGROUPS 8
#define FPG     32
#define NTHREADS 128
#define BTILES  64

// smem byte offsets (all multiples of 16; bank math assumes base % 128 == 0)
#define OFF_B2H 0u          // [64][136] bf16 = 17408
#define OFF_B2L 17408u
#define OFF_B3H 34816u      // [32][72] bf16 = 4608
#define OFF_B3L 39424u
#define OFF_A2H 44032u      // [128][72] bf16 = 18432  (K-half / A3 alias)
#define OFF_A2L 62464u
#define OFF_W1  80896u      // 128 f32
#define OFF_B1v 81408u
#define OFF_B2v 81920u      // 64 f32
#define OFF_B3v 82176u      // 32 f32
#define OFF_W4v 82304u      // 32 f32
#define SMEM_BYTES 82560u   // 82432 + 128 align slack

// ---- global scratch (static: no runtime allocation) ------------------------
__device__ float g_partial[FGROUPS * B_TOTAL];
__device__ float g_xT[F_TOTAL * B_TOTAL];                         // 8 MB
__device__ __align__(16) uint32_t g_BT2H[F_TOTAL * 64 * 64];      // 4 MB
__device__ __align__(16) uint32_t g_BT2L[F_TOTAL * 64 * 64];
__device__ __align__(16) uint32_t g_BT3H[F_TOTAL * 32 * 32];      // 1 MB
__device__ __align__(16) uint32_t g_BT3L[F_TOTAL * 32 * 32];

// ---- helpers ---------------------------------------------------------------
// Pack (v0,v1) -> hi word (truncated bf16 pair, v0 in low half) and
// lo word (rn-bf16 of exact residuals). Error of hi+lo vs v: ~2^-17 |v|.
__device__ __forceinline__ void split2(float v0, float v1,
                                       uint32_t& hi, uint32_t& lo) {
    uint32_t u0 = __float_as_uint(v0), u1 = __float_as_uint(v1);
    asm("prmt.b32 %0, %1, %2, 0x7632;" : "=r"(hi) : "r"(u0), "r"(u1));
    float r0 = __uint_as_float(u0 & 0xFFFF0000u);
    float r1 = __uint_as_float(u1 & 0xFFFF0000u);
    float l0 = v0 - r0, l1 = v1 - r1;
    asm("cvt.rn.bf16x2.f32 %0, %1, %2;" : "=r"(lo) : "f"(l1), "f"(l0));
}

__device__ __forceinline__ void mma16816(float* c, const uint32_t* a,
                                         uint32_t b0, uint32_t b1) {
    asm volatile(
        "mma.sync.aligned.m16n8k16.row.col.f32.bf16.bf16.f32 "
        "{%0,%1,%2,%3}, {%4,%5,%6,%7}, {%8,%9}, {%0,%1,%2,%3};"
        : "+f"(c[0]), "+f"(c[1]), "+f"(c[2]), "+f"(c[3])
        : "r"(a[0]), "r"(a[1]), "r"(a[2]), "r"(a[3]), "r"(b0), "r"(b1));
}

// ---------------------------------------------------------------------------
// prep kernels: transpose x; transpose+bf16-split W2, W3 into [f][n][k] scratch
// ---------------------------------------------------------------------------
__global__ void prep_xT(const float* __restrict__ x) {
    __shared__ float s[32][33];
    int f0 = blockIdx.x * 32, b0 = blockIdx.y * 32;
    int tx = threadIdx.x, ty = threadIdx.y;
    #pragma unroll
    for (int i = 0; i < 4; ++i)
        s[ty + 8 * i][tx] = x[(size_t)(b0 + ty + 8 * i) * F_TOTAL + f0 + tx];
    __syncthreads();
    #pragma unroll
    for (int i = 0; i < 4; ++i)
        g_xT[(size_t)(f0 + ty + 8 * i) * B_TOTAL + b0 + tx] = s[tx][ty + 8 * i];
}

__global__ void prep_w2(const float* __restrict__ W2) {
    __shared__ float s[32][33];
    int f = blockIdx.x;
    int kt = blockIdx.y >> 1, nt = blockIdx.y & 1;
    int k0 = kt * 32, n0 = nt * 32;
    int tx = threadIdx.x, ty = threadIdx.y;
    #pragma unroll
    for (int i = 0; i < 4; ++i)
        s[ty + 8 * i][tx] = W2[((size_t)f * 128 + k0 + ty + 8 * i) * 64 + n0 + tx];
    __syncthreads();
    if (tx < 16) {
        #pragma unroll
        for (int i = 0; i < 4; ++i) {
            int n = ty + 8 * i;
            uint32_t hi, lo;
            split2(s[tx * 2][n], s[tx * 2 + 1][n], hi, lo);
            size_t word = ((size_t)f * 64 + n0 + n) * 64 + kt * 16 + tx;
            g_BT2H[word] = hi;
            g_BT2L[word] = lo;
        }
    }
}

__global__ void prep_w3(const float* __restrict__ W3) {
    __shared__ float s[32][33];
    int f = blockIdx.x;
    int k0 = blockIdx.y * 32;
    int tx = threadIdx.x, ty = threadIdx.y;
    #pragma unroll
    for (int i = 0; i < 4; ++i)
        s[ty + 8 * i][tx] = W3[((size_t)f * 64 + k0 + ty + 8 * i) * 32 + tx];
    __syncthreads();
    if (tx < 16) {
        #pragma unroll
        for (int i = 0; i < 4; ++i) {
            int n = ty + 8 * i;
            uint32_t hi, lo;
            split2(s[tx * 2][n], s[tx * 2 + 1][n], hi, lo);
            size_t word = ((size_t)f * 32 + n) * 32 + blockIdx.y * 16 + tx;
            g_BT3H[word] = hi;
            g_BT3L[word] = lo;
        }
    }
}

// ---------------------------------------------------------------------------
__global__ __launch_bounds__(NTHREADS)
void nam_main(const float* __restrict__ W1, const float* __restrict__ b1,
              const float* __restrict__ b2, const float* __restrict__ b3,
              const float* __restrict__ W4, const float* __restrict__ b4)
{
    extern __shared__ char smem_raw[];
    char* sb = smem_raw + ((128 - ((uintptr_t)smem_raw & 127)) & 127);

    const int tid = threadIdx.x;
    const int lam = tid & 31, w = tid >> 5;
    const int g = lam >> 2, tig = lam & 3;
    const int row = blockIdx.x * NTHREADS + tid;
    const int f0 = blockIdx.y * FPG;

    float acc = 0.0f;

    for (int fi = 0; fi < FPG; ++fi) {
        const int f = f0 + fi;
        __syncthreads();   // all warps done reading BT of previous feature

        // ---- stage BT2 (hi/lo), BT3, misc via conflict-free uint4 copies ----
        {
            const uint4* gh = (const uint4*)((const char*)g_BT2H + (size_t)f * 16384);
            const uint4* gl = (const uint4*)((const char*)g_BT2L + (size_t)f * 16384);
            #pragma unroll
            for (int i = 0; i < 8; ++i) {
                int idx = tid + i * NTHREADS;
                int n = idx >> 4, kk = idx & 15;
                *(uint4*)(sb + OFF_B2H + n * 272 + kk * 16) = gh[idx];
                *(uint4*)(sb + OFF_B2L + n * 272 + kk * 16) = gl[idx];
            }
            const uint4* g3h = (const uint4*)((const char*)g_BT3H + (size_t)f * 4096);
            const uint4* g3l = (const uint4*)((const char*)g_BT3L + (size_t)f * 4096);
            #pragma unroll
            for (int i = 0; i < 2; ++i) {
                int idx = tid + i * NTHREADS;
                int n = idx >> 3, kk = idx & 7;
                *(uint4*)(sb + OFF_B3H + n * 144 + kk * 16) = g3h[idx];
                *(uint4*)(sb + OFF_B3L + n * 144 + kk * 16) = g3l[idx];
            }
            if (tid < 32)
                *(uint4*)(sb + OFF_W1 + tid * 16) = ((const uint4*)(W1 + (size_t)f * 128))[tid];
            else if (tid < 64)
                *(uint4*)(sb + OFF_B1v + (tid - 32) * 16) = ((const uint4*)(b1 + (size_t)f * 128))[tid - 32];
            else if (tid < 80)
                *(uint4*)(sb + OFF_B2v + (tid - 64) * 16) = ((const uint4*)(b2 + (size_t)f * 64))[tid - 64];
            else if (tid < 88)
                *(uint4*)(sb + OFF_B3v + (tid - 80) * 16) = ((const uint4*)(b3 + (size_t)f * 32))[tid - 80];
            else if (tid < 96)
                *(uint4*)(sb + OFF_W4v + (tid - 88) * 16) = ((const uint4*)(W4 + (size_t)f * 32))[tid - 88];
        }
        __syncthreads();

        const float xv = g_xT[(size_t)f * B_TOTAL + row];

        // ---- layer 1 + layer 2 (two K=64 halves), 3-pass split MMA ----
        float acc2[2][8][4] = {};
        const int strowH = (int)OFF_A2H + (w * 32 + lam) * 144;
        const int strowL = (int)OFF_A2L + (w * 32 + lam) * 144;
        const int pofs = (lam >> 3) << 3;   // store-column stagger (bank spread)

        #pragma unroll
        for (int half = 0; half < 2; ++half) {
            #pragma unroll
            for (int pp = 0; pp < 32; ++pp) {
                int p = (pp + pofs) & 31;
                int j = half * 64 + p * 2;
                float2 wv = *(const float2*)(sb + OFF_W1 + j * 4);
                float2 bv = *(const float2*)(sb + OFF_B1v + j * 4);
                float h0 = fmaxf(fmaf(xv, wv.x, bv.x), 0.0f);
                float h1 = fmaxf(fmaf(xv, wv.y, bv.y), 0.0f);
                uint32_t hi, lo;
                split2(h0, h1, hi, lo);
                *(uint32_t*)(sb + strowH + p * 4) = hi;
                *(uint32_t*)(sb + strowL + p * 4) = lo;
            }
            __syncwarp();

            #pragma unroll
            for (int kt = 0; kt < 4; ++kt) {
                uint32_t AH[2][4], AL[2][4];
                #pragma unroll
                for (int mt = 0; mt < 2; ++mt)
                    #pragma unroll
                    for (int i = 0; i < 2; ++i) {
                        int ab = (w * 32 + mt * 16 + i * 8 + g) * 144 + kt * 32 + tig * 4;
                        AH[mt][i]     = *(uint32_t*)(sb + OFF_A2H + ab);
                        AH[mt][i + 2] = *(uint32_t*)(sb + OFF_A2H + ab + 16);
                        AL[mt][i]     = *(uint32_t*)(sb + OFF_A2L + ab);
                        AL[mt][i + 2] = *(uint32_t*)(sb + OFF_A2L + ab + 16);
                    }
                #pragma unroll
                for (int nt = 0; nt < 8; ++nt) {
                    int bb = (nt * 8 + g) * 272 + half * 128 + kt * 32 + tig * 4;
                    uint32_t bh0 = *(uint32_t*)(sb + OFF_B2H + bb);
                    uint32_t bh1 = *(uint32_t*)(sb + OFF_B2H + bb + 16);
                    uint32_t bl0 = *(uint32_t*)(sb + OFF_B2L + bb);
                    uint32_t bl1 = *(uint32_t*)(sb + OFF_B2L + bb + 16);
                    #pragma unroll
                    for (int mt = 0; mt < 2; ++mt) {
                        mma16816(acc2[mt][nt], AH[mt], bh0, bh1);
                        mma16816(acc2[mt][nt], AH[mt], bl0, bl1);
                        mma16816(acc2[mt][nt], AL[mt], bh0, bh1);
                    }
                }
            }
            __syncwarp();   // frag loads done before next half's stores
        }

        // ---- epilogue 2: +b2, relu, split -> A3 (aliases A2 buffers) ----
        #pragma unroll
        for (int mt = 0; mt < 2; ++mt)
            #pragma unroll
            for (int nt = 0; nt < 8; ++nt) {
                int col = nt * 8 + tig * 2;
                float2 b2v = *(const float2*)(sb + OFF_B2v + col * 4);
                float v0 = fmaxf(acc2[mt][nt][0] + b2v.x, 0.0f);
                float v1 = fmaxf(acc2[mt][nt][1] + b2v.y, 0.0f);
                float v2 = fmaxf(acc2[mt][nt][2] + b2v.x, 0.0f);
                float v3 = fmaxf(acc2[mt][nt][3] + b2v.y, 0.0f);
                uint32_t hi0, lo0, hi1, lo1;
                split2(v0, v1, hi0, lo0);
                split2(v2, v3, hi1, lo1);
                int r1 = (w * 32 + mt * 16 + g) * 144 + col * 2;
                int r2 = r1 + 8 * 144;
                *(uint32_t*)(sb + OFF_A2H + r1) = hi0;
                *(uint32_t*)(sb + OFF_A2L + r1) = lo0;
                *(uint32_t*)(sb + OFF_A2H + r2) = hi1;
                *(uint32_t*)(sb + OFF_A2L + r2) = lo1;
            }
        __syncwarp();

        // ---- layer 3: M=32/warp, N=32, K=64, 3-pass split MMA ----
        float acc3[2][4][4] = {};
        #pragma unroll
        for (int kt = 0; kt < 4; ++kt) {
            uint32_t AH[2][4], AL[2][4];
            #pragma unroll
            for (int mt = 0; mt < 2; ++mt)
                #pragma unroll
                for (int i = 0; i < 2; ++i) {
                    int ab = (w * 32 + mt * 16 + i * 8 + g) * 144 + kt * 32 + tig * 4;
                    AH[mt][i]     = *(uint32_t*)(sb + OFF_A2H + ab);
                    AH[mt][i + 2] = *(uint32_t*)(sb + OFF_A2H + ab + 16);
                    AL[mt][i]     = *(uint32_t*)(sb + OFF_A2L + ab);
                    AL[mt][i + 2] = *(uint32_t*)(sb + OFF_A2L + ab + 16);
                }
            #pragma unroll
            for (int nt = 0; nt < 4; ++nt) {
                int bb = (nt * 8 + g) * 144 + kt * 32 + tig * 4;
                uint32_t bh0 = *(uint32_t*)(sb + OFF_B3H + bb);
                uint32_t bh1 = *(uint32_t*)(sb + OFF_B3H + bb + 16);
                uint32_t bl0 = *(uint32_t*)(sb + OFF_B3L + bb);
                uint32_t bl1 = *(uint32_t*)(sb + OFF_B3L + bb + 16);
                #pragma unroll
                for (int mt = 0; mt < 2; ++mt) {
                    mma16816(acc3[mt][nt], AH[mt], bh0, bh1);
                    mma16816(acc3[mt][nt], AH[mt], bl0, bl1);
                    mma16816(acc3[mt][nt], AL[mt], bh0, bh1);
                }
            }
        }

        // ---- epilogue 3: +b3, relu, dot with W4, warp reduce, distribute ----
        {
            float r0 = 0.f, r1 = 0.f, r2 = 0.f, r3 = 0.f;
            #pragma unroll
            for (int mt = 0; mt < 2; ++mt)
                #pragma unroll
                for (int nt = 0; nt < 4; ++nt) {
                    int col = nt * 8 + tig * 2;
                    float2 b3v = *(const float2*)(sb + OFF_B3v + col * 4);
                    float2 w4v = *(const float2*)(sb + OFF_W4v + col * 4);
                    float lo = fmaxf(acc3[mt][nt][0] + b3v.x, 0.f) * w4v.x
                             + fmaxf(acc3[mt][nt][1] + b3v.y, 0.f) * w4v.y;
                    float hi = fmaxf(acc3[mt][nt][2] + b3v.x, 0.f) * w4v.x
                             + fmaxf(acc3[mt][nt][3] + b3v.y, 0.f) * w4v.y;
                    if (mt == 0) { r0 += lo; r1 += hi; }
                    else         { r2 += lo; r3 += hi; }
                }
            #pragma unroll
            for (int d = 1; d <= 2; d <<= 1) {
                r0 += __shfl_xor_sync(0xffffffffu, r0, d);
                r1 += __shfl_xor_sync(0xffffffffu, r1, d);
                r2 += __shfl_xor_sync(0xffffffffu, r2, d);
                r3 += __shfl_xor_sync(0xffffffffu, r3, d);
            }
            int src = (lam & 7) * 4;
            float t0 = __shfl_sync(0xffffffffu, r0, src);
            float t1 = __shfl_sync(0xffffffffu, r1, src);
            float t2 = __shfl_sync(0xffffffffu, r2, src);
            float t3 = __shfl_sync(0xffffffffu, r3, src);
            int sel = lam >> 3;
            float fout = (sel == 0) ? t0 : (sel == 1) ? t1 : (sel == 2) ? t2 : t3;
            acc += fout + __ldg(b4 + f);
        }
    }

    g_partial[blockIdx.y * B_TOTAL + row] = acc;
}

// ---------------------------------------------------------------------------
__global__ void nam_reduce(const float* __restrict__ bias,
                           float* __restrict__ out)
{
    const int b = blockIdx.x * blockDim.x + threadIdx.x;
    if (b < B_TOTAL) {
        float s = bias[0];
        #pragma unroll
        for (int g2 = 0; g2 < FGROUPS; ++g2)
            s += g_partial[g2 * B_TOTAL + b];
        out[b] = s;
    }
}

// ---------------------------------------------------------------------------
extern "C" void kernel_launch(void* const* d_in, const int* in_sizes, int n_in,
                              void* d_out, int out_size)
{
    (void)in_sizes; (void)n_in; (void)out_size;
    const float* x    = (const float*)d_in[0];
    const float* W1   = (const float*)d_in[1];
    const float* b1   = (const float*)d_in[2];
    const float* W2   = (const float*)d_in[3];
    const float* b2   = (const float*)d_in[4];
    const float* W3   = (const float*)d_in[5];
    const float* b3   = (const float*)d_in[6];
    const float* W4   = (const float*)d_in[7];
    const float* b4   = (const float*)d_in[8];
    const float* bias = (const float*)d_in[9];
    float* out = (float*)d_out;

    cudaFuncSetAttribute(nam_main, cudaFuncAttributeMaxDynamicSharedMemorySize,
                         SMEM_BYTES);

    prep_xT<<<dim3(F_TOTAL / 32, B_TOTAL / 32), dim3(32, 8)>>>(x);
    prep_w2<<<dim3(F_TOTAL, 8), dim3(32, 8)>>>(W2);
    prep_w3<<<dim3(F_TOTAL, 2), dim3(32, 8)>>>(W3);

    nam_main<<<dim3(BTILES, FGROUPS), NTHREADS, SMEM_BYTES>>>(W1, b1, b2, b3, W4, b4);
    nam_reduce<<<(B_TOTAL + 255) / 256, 256>>>(bias, out);
}

// round 9
// speedup vs baseline: 5.8657x; 2.2860x over previous
#include <cuda_runtime.h>
#include <cuda_fp16.h>
#include <cstdint>

// ---------------------------------------------------------------------------
// NAM via warp-level f16 mma.sync, fully register-resident activations.
//   layer2: A = f16(h1) single, B = 2-term f16 split  -> 2 passes
//   layer3: A = 2-term split of relu(C2+b2) (from regs), B split -> 3 passes
// Weights pre-transformed into per-lane MMA-fragment records by prep kernels.
// R7 fix: sB2 must hold 2048 uint4 records (32 KB), staging 16 iterations.
// ---------------------------------------------------------------------------

#define B_TOTAL 8192
#define F_TOTAL 256
#define FGROUPS 16
#define FPG     16
#define NTHREADS 128
#define BTILES  64

__device__ float g_partial[FGROUPS * B_TOTAL];
__device__ float g_xT[F_TOTAL * B_TOTAL];                       // 8 MB
__device__ __align__(16) uint4 g_B2[F_TOTAL * 2048];            // 16 MB [f][half][kt][nt][lane]
__device__ __align__(16) uint4 g_B3[F_TOTAL * 512];             // 4 MB [f][kt][nt][lane]

// ---- helpers ---------------------------------------------------------------
__device__ __forceinline__ uint32_t packh2(float v0, float v1) {
    uint32_t r;                     // low half = v0, high half = v1
    asm("cvt.rn.f16x2.f32 %0, %1, %2;" : "=r"(r) : "f"(v1), "f"(v0));
    return r;
}
__device__ __forceinline__ void splith2(float v0, float v1,
                                        uint32_t& hi, uint32_t& lo) {
    hi = packh2(v0, v1);
    __half2 h = *(__half2*)&hi;
    float2 r = __half22float2(h);
    lo = packh2(v0 - r.x, v1 - r.y);
}
__device__ __forceinline__ void mma16816(float* c, const uint32_t* a,
                                         uint32_t b0, uint32_t b1) {
    asm volatile(
        "mma.sync.aligned.m16n8k16.row.col.f32.f16.f16.f32 "
        "{%0,%1,%2,%3}, {%4,%5,%6,%7}, {%8,%9}, {%0,%1,%2,%3};"
        : "+f"(c[0]), "+f"(c[1]), "+f"(c[2]), "+f"(c[3])
        : "r"(a[0]), "r"(a[1]), "r"(a[2]), "r"(a[3]), "r"(b0), "r"(b1));
}

// ---------------------------------------------------------------------------
// prep kernels
// ---------------------------------------------------------------------------
__global__ void prep_xT(const float* __restrict__ x) {
    __shared__ float s[32][33];
    int f0 = blockIdx.x * 32, b0 = blockIdx.y * 32;
    int tx = threadIdx.x, ty = threadIdx.y;
    #pragma unroll
    for (int i = 0; i < 4; ++i)
        s[ty + 8 * i][tx] = x[(size_t)(b0 + ty + 8 * i) * F_TOTAL + f0 + tx];
    __syncthreads();
    #pragma unroll
    for (int i = 0; i < 4; ++i)
        g_xT[(size_t)(f0 + ty + 8 * i) * B_TOTAL + b0 + tx] = s[tx][ty + 8 * i];
}

// W2[f]: [128 k][64 n] -> fragment records: e = ((half*4+kt)*8+nt)*32+lane
__global__ void prep_w2(const float* __restrict__ W2) {
    __shared__ float s[128 * 64];
    const int f = blockIdx.x, tid = threadIdx.x;
    for (int i = tid; i < 8192; i += 256) s[i] = W2[(size_t)f * 8192 + i];
    __syncthreads();
    for (int e = tid; e < 2048; e += 256) {
        int lane = e & 31, nt = (e >> 5) & 7, kt = (e >> 8) & 3, half = (e >> 10) & 1;
        int g = lane >> 2, tig = lane & 3;
        int n = nt * 8 + g;
        int k0 = half * 64 + kt * 16 + tig * 2;
        uint32_t h0, l0, h1, l1;
        splith2(s[k0 * 64 + n],       s[(k0 + 1) * 64 + n], h0, l0);
        splith2(s[(k0 + 8) * 64 + n], s[(k0 + 9) * 64 + n], h1, l1);
        g_B2[(size_t)f * 2048 + e] = make_uint4(h0, h1, l0, l1);
    }
}

// W3[f]: [64 k][32 n] -> records: e = (kt*4+nt)*32+lane
__global__ void prep_w3(const float* __restrict__ W3) {
    __shared__ float s[64 * 32];
    const int f = blockIdx.x, tid = threadIdx.x;
    for (int i = tid; i < 2048; i += 256) s[i] = W3[(size_t)f * 2048 + i];
    __syncthreads();
    for (int e = tid; e < 512; e += 256) {
        int lane = e & 31, nt = (e >> 5) & 3, kt = (e >> 7) & 3;
        int g = lane >> 2, tig = lane & 3;
        int n = nt * 8 + g;
        int k0 = kt * 16 + tig * 2;
        uint32_t h0, l0, h1, l1;
        splith2(s[k0 * 32 + n],       s[(k0 + 1) * 32 + n], h0, l0);
        splith2(s[(k0 + 8) * 32 + n], s[(k0 + 9) * 32 + n], h1, l1);
        g_B3[(size_t)f * 512 + e] = make_uint4(h0, h1, l0, l1);
    }
}

// ---------------------------------------------------------------------------
__global__ __launch_bounds__(NTHREADS)
void nam_main(const float* __restrict__ W1, const float* __restrict__ b1,
              const float* __restrict__ b2, const float* __restrict__ b3,
              const float* __restrict__ W4, const float* __restrict__ b4)
{
    __shared__ __align__(16) uint4 sB2[2048];           // 32 KB (full record set)
    __shared__ __align__(16) uint4 sB3[512];            // 8 KB
    __shared__ __align__(16) float sW1[128], sB1[128];
    __shared__ __align__(16) float sB2v[64], sB3v[32], sW4v[32];

    const int tid = threadIdx.x;
    const int lam = tid & 31;
    const int g = lam >> 2, tig = lam & 3;
    const int row = blockIdx.x * NTHREADS + tid;
    const int f0 = blockIdx.y * FPG;

    float acc = 0.0f;

    for (int fi = 0; fi < FPG; ++fi) {
        const int f = f0 + fi;
        __syncthreads();   // previous feature's readers done

        // ---- stage fragment records + misc (contiguous, conflict-free) ----
        {
            const uint4* s2 = g_B2 + (size_t)f * 2048;
            const uint4* s3 = g_B3 + (size_t)f * 512;
            #pragma unroll
            for (int i = 0; i < 16; ++i)
                sB2[tid + i * NTHREADS] = s2[tid + i * NTHREADS];
            #pragma unroll
            for (int i = 0; i < 4; ++i)
                sB3[tid + i * NTHREADS] = s3[tid + i * NTHREADS];
            if (tid < 32)
                ((float4*)sW1)[tid] = ((const float4*)(W1 + (size_t)f * 128))[tid];
            else if (tid < 64)
                ((float4*)sB1)[tid - 32] = ((const float4*)(b1 + (size_t)f * 128))[tid - 32];
            else if (tid < 80)
                ((float4*)sB2v)[tid - 64] = ((const float4*)(b2 + (size_t)f * 64))[tid - 64];
            else if (tid < 88)
                ((float4*)sB3v)[tid - 80] = ((const float4*)(b3 + (size_t)f * 32))[tid - 80];
            else if (tid < 96)
                ((float4*)sW4v)[tid - 88] = ((const float4*)(W4 + (size_t)f * 32))[tid - 88];
        }
        __syncthreads();

        // x for this lane's 4 fragment rows (g, g+8, g+16, g+24)
        const float xv = g_xT[(size_t)f * B_TOTAL + row];
        float xr[4];
        #pragma unroll
        for (int j = 0; j < 4; ++j)
            xr[j] = __shfl_sync(0xffffffffu, xv, g + 8 * j);

        // ---- layer 1 (registers) + layer 2 MMA, 2-pass ----
        float acc2[2][8][4] = {};
        #pragma unroll
        for (int half = 0; half < 2; ++half) {
            #pragma unroll
            for (int kt = 0; kt < 4; ++kt) {
                const int c = half * 64 + kt * 16 + tig * 2;
                float2 wa = *(const float2*)(sW1 + c);
                float2 wb = *(const float2*)(sW1 + c + 8);
                float2 ba = *(const float2*)(sB1 + c);
                float2 bbv = *(const float2*)(sB1 + c + 8);
                uint32_t A[2][4];
                #pragma unroll
                for (int mt = 0; mt < 2; ++mt)
                    #pragma unroll
                    for (int i2 = 0; i2 < 2; ++i2) {
                        float xx = xr[mt * 2 + i2];
                        float h0 = fmaxf(fmaf(xx, wa.x, ba.x), 0.0f);
                        float h1 = fmaxf(fmaf(xx, wa.y, ba.y), 0.0f);
                        float h2 = fmaxf(fmaf(xx, wb.x, bbv.x), 0.0f);
                        float h3 = fmaxf(fmaf(xx, wb.y, bbv.y), 0.0f);
                        A[mt][i2]     = packh2(h0, h1);
                        A[mt][i2 + 2] = packh2(h2, h3);
                    }
                const uint4* bp = sB2 + (size_t)((half * 4 + kt) * 8) * 32;
                #pragma unroll
                for (int nt = 0; nt < 8; ++nt) {
                    uint4 B = bp[nt * 32 + lam];
                    #pragma unroll
                    for (int mt = 0; mt < 2; ++mt) {
                        mma16816(acc2[mt][nt], A[mt], B.x, B.y);   // A*BH
                        mma16816(acc2[mt][nt], A[mt], B.z, B.w);   // A*BL
                    }
                }
            }
        }

        // ---- epi2 + layer 3 fused per kt3: C2 frags ARE the A3 frags ----
        float acc3[2][4][4] = {};
        #pragma unroll
        for (int kt3 = 0; kt3 < 4; ++kt3) {
            uint32_t a3h[2][4], a3l[2][4];
            #pragma unroll
            for (int mt = 0; mt < 2; ++mt)
                #pragma unroll
                for (int j = 0; j < 2; ++j) {
                    int nt = kt3 * 2 + j;
                    float2 bv = *(const float2*)(sB2v + nt * 8 + 2 * tig);
                    float v0 = fmaxf(acc2[mt][nt][0] + bv.x, 0.0f);
                    float v1 = fmaxf(acc2[mt][nt][1] + bv.y, 0.0f);
                    float v2 = fmaxf(acc2[mt][nt][2] + bv.x, 0.0f);
                    float v3 = fmaxf(acc2[mt][nt][3] + bv.y, 0.0f);
                    splith2(v0, v1, a3h[mt][j * 2],     a3l[mt][j * 2]);
                    splith2(v2, v3, a3h[mt][j * 2 + 1], a3l[mt][j * 2 + 1]);
                }
            const uint4* bp = sB3 + (size_t)(kt3 * 4) * 32;
            #pragma unroll
            for (int nt = 0; nt < 4; ++nt) {
                uint4 B = bp[nt * 32 + lam];
                #pragma unroll
                for (int mt = 0; mt < 2; ++mt) {
                    mma16816(acc3[mt][nt], a3h[mt], B.x, B.y);   // AH*BH
                    mma16816(acc3[mt][nt], a3h[mt], B.z, B.w);   // AH*BL
                    mma16816(acc3[mt][nt], a3l[mt], B.x, B.y);   // AL*BH
                }
            }
        }

        // ---- epi3: +b3, relu, dot W4, warp reduce, distribute ----
        {
            float r0 = 0.f, r1 = 0.f, r2 = 0.f, r3 = 0.f;
            #pragma unroll
            for (int mt = 0; mt < 2; ++mt)
                #pragma unroll
                for (int nt = 0; nt < 4; ++nt) {
                    int col = nt * 8 + tig * 2;
                    float2 b3v = *(const float2*)(sB3v + col);
                    float2 w4v = *(const float2*)(sW4v + col);
                    float lo = fmaxf(acc3[mt][nt][0] + b3v.x, 0.f) * w4v.x
                             + fmaxf(acc3[mt][nt][1] + b3v.y, 0.f) * w4v.y;
                    float hi = fmaxf(acc3[mt][nt][2] + b3v.x, 0.f) * w4v.x
                             + fmaxf(acc3[mt][nt][3] + b3v.y, 0.f) * w4v.y;
                    if (mt == 0) { r0 += lo; r1 += hi; }
                    else         { r2 += lo; r3 += hi; }
                }
            #pragma unroll
            for (int d = 1; d <= 2; d <<= 1) {
                r0 += __shfl_xor_sync(0xffffffffu, r0, d);
                r1 += __shfl_xor_sync(0xffffffffu, r1, d);
                r2 += __shfl_xor_sync(0xffffffffu, r2, d);
                r3 += __shfl_xor_sync(0xffffffffu, r3, d);
            }
            int src = (lam & 7) * 4;
            float t0 = __shfl_sync(0xffffffffu, r0, src);
            float t1 = __shfl_sync(0xffffffffu, r1, src);
            float t2 = __shfl_sync(0xffffffffu, r2, src);
            float t3 = __shfl_sync(0xffffffffu, r3, src);
            int sel = lam >> 3;
            float fout = (sel == 0) ? t0 : (sel == 1) ? t1 : (sel == 2) ? t2 : t3;
            acc += fout + __ldg(b4 + f);
        }
    }

    g_partial[blockIdx.y * B_TOTAL + row] = acc;
}

// ---------------------------------------------------------------------------
__global__ void nam_reduce(const float* __restrict__ bias,
                           float* __restrict__ out)
{
    const int b = blockIdx.x * blockDim.x + threadIdx.x;
    if (b < B_TOTAL) {
        float s = bias[0];
        #pragma unroll
        for (int g2 = 0; g2 < FGROUPS; ++g2)
            s += g_partial[g2 * B_TOTAL + b];
        out[b] = s;
    }
}

// ---------------------------------------------------------------------------
extern "C" void kernel_launch(void* const* d_in, const int* in_sizes, int n_in,
                              void* d_out, int out_size)
{
    (void)in_sizes; (void)n_in; (void)out_size;
    const float* x    = (const float*)d_in[0];
    const float* W1   = (const float*)d_in[1];
    const float* b1   = (const float*)d_in[2];
    const float* W2   = (const float*)d_in[3];
    const float* b2   = (const float*)d_in[4];
    const float* W3   = (const float*)d_in[5];
    const float* b3   = (const float*)d_in[6];
    const float* W4   = (const float*)d_in[7];
    const float* b4   = (const float*)d_in[8];
    const float* bias = (const float*)d_in[9];
    float* out = (float*)d_out;

    prep_xT<<<dim3(F_TOTAL / 32, B_TOTAL / 32), dim3(32, 8)>>>(x);
    prep_w2<<<F_TOTAL, 256>>>(W2);
    prep_w3<<<F_TOTAL, 256>>>(W3);

    nam_main<<<dim3(BTILES, FGROUPS), NTHREADS>>>(W1, b1, b2, b3, W4, b4);
    nam_reduce<<<(B_TOTAL + 255) / 256, 256>>>(bias, out);
}

// round 10
// speedup vs baseline: 8.9871x; 1.5322x over previous
#include <cuda_runtime.h>
#include <cuda_fp16.h>
#include <cstdint>

// ---------------------------------------------------------------------------
// NAM via warp-level f16 mma.sync, register-resident activations.
//   layer2: A = f16(h1), B = f16(W2)            -> 1 pass   (128 MMAs/warp-feat)
//   layer3: A = 2-term split, B = 2-term split  -> 3 passes (96 MMAs/warp-feat)
// Weights pre-transformed into per-lane MMA-fragment records; cp.async
// double-buffered staging overlaps the next feature's weight fetch with MMA.
// ---------------------------------------------------------------------------

#define B_TOTAL 8192
#define F_TOTAL 256
#define FGROUPS 16
#define FPG     16
#define NTHREADS 128
#define BTILES  64

// dynamic smem layout (bytes)
#define SM_B2   0u          // [2][2048] uint2 = 32768
#define SM_B3   32768u      // [2][512] uint4  = 16384
#define SM_MISC 49152u      // [2][384] float  = 3072
#define SMEM_BYTES 52224u

__device__ float g_partial[FGROUPS * B_TOTAL];
__device__ float g_xT[F_TOTAL * B_TOTAL];                       // 8 MB
__device__ __align__(16) uint2 g_B2[F_TOTAL * 2048];            // 4 MB [f][half][kt][nt][lane]
__device__ __align__(16) uint4 g_B3[F_TOTAL * 512];             // 4 MB [f][kt][nt][lane]

// ---- helpers ---------------------------------------------------------------
__device__ __forceinline__ uint32_t packh2(float v0, float v1) {
    uint32_t r;                     // low half = v0, high half = v1
    asm("cvt.rn.f16x2.f32 %0, %1, %2;" : "=r"(r) : "f"(v1), "f"(v0));
    return r;
}
__device__ __forceinline__ void splith2(float v0, float v1,
                                        uint32_t& hi, uint32_t& lo) {
    hi = packh2(v0, v1);
    __half2 h = *(__half2*)&hi;
    float2 r = __half22float2(h);
    lo = packh2(v0 - r.x, v1 - r.y);
}
__device__ __forceinline__ void mma16816(float* c, const uint32_t* a,
                                         uint32_t b0, uint32_t b1) {
    asm volatile(
        "mma.sync.aligned.m16n8k16.row.col.f32.f16.f16.f32 "
        "{%0,%1,%2,%3}, {%4,%5,%6,%7}, {%8,%9}, {%0,%1,%2,%3};"
        : "+f"(c[0]), "+f"(c[1]), "+f"(c[2]), "+f"(c[3])
        : "r"(a[0]), "r"(a[1]), "r"(a[2]), "r"(a[3]), "r"(b0), "r"(b1));
}
__device__ __forceinline__ void cp16(uint32_t dst, const void* src) {
    asm volatile("cp.async.cg.shared.global [%0], [%1], 16;"
                 :: "r"(dst), "l"(src));
}
#define CP_COMMIT() asm volatile("cp.async.commit_group;" ::: "memory")
#define CP_WAIT0()  asm volatile("cp.async.wait_group 0;" ::: "memory")

// ---------------------------------------------------------------------------
// prep kernels
// ---------------------------------------------------------------------------
__global__ void prep_xT(const float* __restrict__ x) {
    __shared__ float s[32][33];
    int f0 = blockIdx.x * 32, b0 = blockIdx.y * 32;
    int tx = threadIdx.x, ty = threadIdx.y;
    #pragma unroll
    for (int i = 0; i < 4; ++i)
        s[ty + 8 * i][tx] = x[(size_t)(b0 + ty + 8 * i) * F_TOTAL + f0 + tx];
    __syncthreads();
    #pragma unroll
    for (int i = 0; i < 4; ++i)
        g_xT[(size_t)(f0 + ty + 8 * i) * B_TOTAL + b0 + tx] = s[tx][ty + 8 * i];
}

// W2[f]: [128 k][64 n] -> f16 records: e = ((half*4+kt)*8+nt)*32+lane
__global__ void prep_w2(const float* __restrict__ W2) {
    __shared__ float s[128 * 64];
    const int f = blockIdx.x, tid = threadIdx.x;
    for (int i = tid; i < 8192; i += 256) s[i] = W2[(size_t)f * 8192 + i];
    __syncthreads();
    for (int e = tid; e < 2048; e += 256) {
        int lane = e & 31, nt = (e >> 5) & 7, kt = (e >> 8) & 3, half = (e >> 10) & 1;
        int g = lane >> 2, tig = lane & 3;
        int n = nt * 8 + g;
        int k0 = half * 64 + kt * 16 + tig * 2;
        uint32_t h0 = packh2(s[k0 * 64 + n],       s[(k0 + 1) * 64 + n]);
        uint32_t h1 = packh2(s[(k0 + 8) * 64 + n], s[(k0 + 9) * 64 + n]);
        g_B2[(size_t)f * 2048 + e] = make_uint2(h0, h1);
    }
}

// W3[f]: [64 k][32 n] -> split records: e = (kt*4+nt)*32+lane
__global__ void prep_w3(const float* __restrict__ W3) {
    __shared__ float s[64 * 32];
    const int f = blockIdx.x, tid = threadIdx.x;
    for (int i = tid; i < 2048; i += 256) s[i] = W3[(size_t)f * 2048 + i];
    __syncthreads();
    for (int e = tid; e < 512; e += 256) {
        int lane = e & 31, nt = (e >> 5) & 3, kt = (e >> 7) & 3;
        int g = lane >> 2, tig = lane & 3;
        int n = nt * 8 + g;
        int k0 = kt * 16 + tig * 2;
        uint32_t h0, l0, h1, l1;
        splith2(s[k0 * 32 + n],       s[(k0 + 1) * 32 + n], h0, l0);
        splith2(s[(k0 + 8) * 32 + n], s[(k0 + 9) * 32 + n], h1, l1);
        g_B3[(size_t)f * 512 + e] = make_uint4(h0, h1, l0, l1);
    }
}

// ---------------------------------------------------------------------------
__global__ __launch_bounds__(NTHREADS)
void nam_main(const float* __restrict__ W1, const float* __restrict__ b1,
              const float* __restrict__ b2, const float* __restrict__ b3,
              const float* __restrict__ W4, const float* __restrict__ b4)
{
    extern __shared__ __align__(16) char smem[];
    const uint32_t sbase = (uint32_t)__cvta_generic_to_shared(smem);

    const int tid = threadIdx.x;
    const int lam = tid & 31;
    const int g = lam >> 2, tig = lam & 3;
    const int row = blockIdx.x * NTHREADS + tid;
    const int f0 = blockIdx.y * FPG;

    // ---- cp.async staging of one feature's records into buffer `buf` ----
    auto stage = [&](int buf, int f) {
        const char* s2 = (const char*)(g_B2 + (size_t)f * 2048);
        uint32_t d2 = sbase + SM_B2 + (uint32_t)buf * 16384u;
        #pragma unroll
        for (int i = 0; i < 8; ++i) {
            int t = tid + i * NTHREADS;
            cp16(d2 + t * 16, s2 + t * 16);
        }
        const char* s3 = (const char*)(g_B3 + (size_t)f * 512);
        uint32_t d3 = sbase + SM_B3 + (uint32_t)buf * 8192u;
        #pragma unroll
        for (int i = 0; i < 4; ++i) {
            int t = tid + i * NTHREADS;
            cp16(d3 + t * 16, s3 + t * 16);
        }
        uint32_t dm = sbase + SM_MISC + (uint32_t)buf * 1536u;
        if (tid < 32)
            cp16(dm + tid * 16, W1 + (size_t)f * 128 + tid * 4);
        else if (tid < 64)
            cp16(dm + 512 + (tid - 32) * 16, b1 + (size_t)f * 128 + (tid - 32) * 4);
        else if (tid < 80)
            cp16(dm + 1024 + (tid - 64) * 16, b2 + (size_t)f * 64 + (tid - 64) * 4);
        else if (tid < 88)
            cp16(dm + 1280 + (tid - 80) * 16, b3 + (size_t)f * 32 + (tid - 80) * 4);
        else if (tid < 96)
            cp16(dm + 1408 + (tid - 88) * 16, W4 + (size_t)f * 32 + (tid - 88) * 4);
    };

    float acc = 0.0f;

    stage(0, f0);
    CP_COMMIT();

    for (int fi = 0; fi < FPG; ++fi) {
        const int f = f0 + fi;
        const int cur = fi & 1;

        const float xv = g_xT[(size_t)f * B_TOTAL + row];   // hoisted LDG

        CP_WAIT0();
        __syncthreads();          // cur buffer ready; prev buffer fully consumed

        if (fi + 1 < FPG) {       // prefetch next feature into the other buffer
            stage(1 - cur, f + 1);
            CP_COMMIT();
        }

        const uint2* sB2 = (const uint2*)(smem + SM_B2) + cur * 2048;
        const uint4* sB3 = (const uint4*)(smem + SM_B3) + cur * 512;
        const float* sM  = (const float*)(smem + SM_MISC) + cur * 384;
        const float* sW1 = sM;
        const float* sB1 = sM + 128;
        const float* sB2v = sM + 256;
        const float* sB3v = sM + 320;
        const float* sW4v = sM + 352;

        float xr[4];
        #pragma unroll
        for (int j = 0; j < 4; ++j)
            xr[j] = __shfl_sync(0xffffffffu, xv, g + 8 * j);

        // ---- layer 1 (registers) + layer 2 MMA, single f16 pass ----
        float acc2[2][8][4] = {};
        #pragma unroll
        for (int half = 0; half < 2; ++half) {
            #pragma unroll
            for (int kt = 0; kt < 4; ++kt) {
                const int c = half * 64 + kt * 16 + tig * 2;
                float2 wa = *(const float2*)(sW1 + c);
                float2 wb = *(const float2*)(sW1 + c + 8);
                float2 ba = *(const float2*)(sB1 + c);
                float2 bbv = *(const float2*)(sB1 + c + 8);
                uint32_t A[2][4];
                #pragma unroll
                for (int mt = 0; mt < 2; ++mt)
                    #pragma unroll
                    for (int i2 = 0; i2 < 2; ++i2) {
                        float xx = xr[mt * 2 + i2];
                        float h0 = fmaxf(fmaf(xx, wa.x, ba.x), 0.0f);
                        float h1 = fmaxf(fmaf(xx, wa.y, ba.y), 0.0f);
                        float h2 = fmaxf(fmaf(xx, wb.x, bbv.x), 0.0f);
                        float h3 = fmaxf(fmaf(xx, wb.y, bbv.y), 0.0f);
                        A[mt][i2]     = packh2(h0, h1);
                        A[mt][i2 + 2] = packh2(h2, h3);
                    }
                const uint2* bp = sB2 + ((half * 4 + kt) * 8) * 32;
                #pragma unroll
                for (int nt = 0; nt < 8; ++nt) {
                    uint2 B = bp[nt * 32 + lam];
                    #pragma unroll
                    for (int mt = 0; mt < 2; ++mt)
                        mma16816(acc2[mt][nt], A[mt], B.x, B.y);
                }
            }
        }

        // ---- epi2 + layer 3 fused per kt3: C2 frags ARE the A3 frags ----
        float acc3[2][4][4] = {};
        #pragma unroll
        for (int kt3 = 0; kt3 < 4; ++kt3) {
            uint32_t a3h[2][4], a3l[2][4];
            #pragma unroll
            for (int mt = 0; mt < 2; ++mt)
                #pragma unroll
                for (int j = 0; j < 2; ++j) {
                    int nt = kt3 * 2 + j;
                    float2 bv = *(const float2*)(sB2v + nt * 8 + 2 * tig);
                    float v0 = fmaxf(acc2[mt][nt][0] + bv.x, 0.0f);
                    float v1 = fmaxf(acc2[mt][nt][1] + bv.y, 0.0f);
                    float v2 = fmaxf(acc2[mt][nt][2] + bv.x, 0.0f);
                    float v3 = fmaxf(acc2[mt][nt][3] + bv.y, 0.0f);
                    splith2(v0, v1, a3h[mt][j * 2],     a3l[mt][j * 2]);
                    splith2(v2, v3, a3h[mt][j * 2 + 1], a3l[mt][j * 2 + 1]);
                }
            const uint4* bp = sB3 + (kt3 * 4) * 32;
            #pragma unroll
            for (int nt = 0; nt < 4; ++nt) {
                uint4 B = bp[nt * 32 + lam];
                #pragma unroll
                for (int mt = 0; mt < 2; ++mt) {
                    mma16816(acc3[mt][nt], a3h[mt], B.x, B.y);   // AH*BH
                    mma16816(acc3[mt][nt], a3h[mt], B.z, B.w);   // AH*BL
                    mma16816(acc3[mt][nt], a3l[mt], B.x, B.y);   // AL*BH
                }
            }
        }

        // ---- epi3: +b3, relu, dot W4, warp reduce, distribute ----
        {
            float r0 = 0.f, r1 = 0.f, r2 = 0.f, r3 = 0.f;
            #pragma unroll
            for (int mt = 0; mt < 2; ++mt)
                #pragma unroll
                for (int nt = 0; nt < 4; ++nt) {
                    int col = nt * 8 + tig * 2;
                    float2 b3v = *(const float2*)(sB3v + col);
                    float2 w4v = *(const float2*)(sW4v + col);
                    float lo = fmaxf(acc3[mt][nt][0] + b3v.x, 0.f) * w4v.x
                             + fmaxf(acc3[mt][nt][1] + b3v.y, 0.f) * w4v.y;
                    float hi = fmaxf(acc3[mt][nt][2] + b3v.x, 0.f) * w4v.x
                             + fmaxf(acc3[mt][nt][3] + b3v.y, 0.f) * w4v.y;
                    if (mt == 0) { r0 += lo; r1 += hi; }
                    else         { r2 += lo; r3 += hi; }
                }
            #pragma unroll
            for (int d = 1; d <= 2; d <<= 1) {
                r0 += __shfl_xor_sync(0xffffffffu, r0, d);
                r1 += __shfl_xor_sync(0xffffffffu, r1, d);
                r2 += __shfl_xor_sync(0xffffffffu, r2, d);
                r3 += __shfl_xor_sync(0xffffffffu, r3, d);
            }
            int src = (lam & 7) * 4;
            float t0 = __shfl_sync(0xffffffffu, r0, src);
            float t1 = __shfl_sync(0xffffffffu, r1, src);
            float t2 = __shfl_sync(0xffffffffu, r2, src);
            float t3 = __shfl_sync(0xffffffffu, r3, src);
            int sel = lam >> 3;
            float fout = (sel == 0) ? t0 : (sel == 1) ? t1 : (sel == 2) ? t2 : t3;
            acc += fout + __ldg(b4 + f);
        }
    }

    g_partial[blockIdx.y * B_TOTAL + row] = acc;
}

// ---------------------------------------------------------------------------
__global__ void nam_reduce(const float* __restrict__ bias,
                           float* __restrict__ out)
{
    const int b = blockIdx.x * blockDim.x + threadIdx.x;
    if (b < B_TOTAL) {
        float s = bias[0];
        #pragma unroll
        for (int g2 = 0; g2 < FGROUPS; ++g2)
            s += g_partial[g2 * B_TOTAL + b];
        out[b] = s;
    }
}

// ---------------------------------------------------------------------------
extern "C" void kernel_launch(void* const* d_in, const int* in_sizes, int n_in,
                              void* d_out, int out_size)
{
    (void)in_sizes; (void)n_in; (void)out_size;
    const float* x    = (const float*)d_in[0];
    const float* W1   = (const float*)d_in[1];
    const float* b1   = (const float*)d_in[2];
    const float* W2   = (const float*)d_in[3];
    const float* b2   = (const float*)d_in[4];
    const float* W3   = (const float*)d_in[5];
    const float* b3   = (const float*)d_in[6];
    const float* W4   = (const float*)d_in[7];
    const float* b4   = (const float*)d_in[8];
    const float* bias = (const float*)d_in[9];
    float* out = (float*)d_out;

    cudaFuncSetAttribute(nam_main, cudaFuncAttributeMaxDynamicSharedMemorySize,
                         SMEM_BYTES);

    prep_xT<<<dim3(F_TOTAL / 32, B_TOTAL / 32), dim3(32, 8)>>>(x);
    prep_w2<<<F_TOTAL, 256>>>(W2);
    prep_w3<<<F_TOTAL, 256>>>(W3);

    nam_main<<<dim3(BTILES, FGROUPS), NTHREADS, SMEM_BYTES>>>(W1, b1, b2, b3, W4, b4);
    nam_reduce<<<(B_TOTAL + 255) / 256, 256>>>(bias, out);
}

// round 11
// speedup vs baseline: 11.3892x; 1.2673x over previous
#include <cuda_runtime.h>
#include <cuda_fp16.h>
#include <cstdint>

// ---------------------------------------------------------------------------
// NAM via warp-level f16 mma.sync, register-resident activations.
//   layer1: f16x2 HFMA2/HMAX2 directly into A-fragments (weights pre-packed)
//   layer2: A = f16(h1), B = f16(W2)                    -> 1 pass (128 MMAs)
//   layer3: A = f16 single, B = 2-term f16 split        -> 2 passes (64 MMAs)
// Weights pre-transformed into per-lane MMA-fragment records; cp.async
// double-buffered staging overlaps the next feature's weight fetch with MMA.
// ---------------------------------------------------------------------------

#define B_TOTAL 8192
#define F_TOTAL 256
#define FGROUPS 32
#define FPG     8
#define NTHREADS 128
#define BTILES  64

// dynamic smem layout (bytes)
#define SM_B2   0u          // [2][2048] uint2 = 32768
#define SM_B3   32768u      // [2][512] uint4  = 16384
#define SM_WB   49152u      // [2][256] uint4  = 8192
#define SM_MISC 57344u      // [2][128] float  = 1024
#define SMEM_BYTES 58368u

__device__ float g_partial[FGROUPS * B_TOTAL];
__device__ float g_xT[F_TOTAL * B_TOTAL];                       // 8 MB
__device__ __align__(16) uint2 g_B2[F_TOTAL * 2048];            // 4 MB [f][half][kt][nt][lane]
__device__ __align__(16) uint4 g_B3[F_TOTAL * 512];             // 4 MB [f][kt][nt][lane]
__device__ __align__(16) uint4 g_WB[F_TOTAL * 256];             // 1 MB [f][half*4+kt][lane]

// ---- helpers ---------------------------------------------------------------
__device__ __forceinline__ uint32_t packh2(float v0, float v1) {
    uint32_t r;                     // low half = v0, high half = v1
    asm("cvt.rn.f16x2.f32 %0, %1, %2;" : "=r"(r) : "f"(v1), "f"(v0));
    return r;
}
__device__ __forceinline__ void splith2(float v0, float v1,
                                        uint32_t& hi, uint32_t& lo) {
    hi = packh2(v0, v1);
    __half2 h = *(__half2*)&hi;
    float2 r = __half22float2(h);
    lo = packh2(v0 - r.x, v1 - r.y);
}
__device__ __forceinline__ uint32_t hfma2_relu(uint32_t x, uint32_t w, uint32_t b) {
    uint32_t t;
    asm("fma.rn.f16x2 %0, %1, %2, %3;" : "=r"(t) : "r"(x), "r"(w), "r"(b));
    uint32_t z;
    asm("max.f16x2 %0, %1, %2;" : "=r"(z) : "r"(t), "r"(0u));
    return z;
}
__device__ __forceinline__ void mma16816(float* c, const uint32_t* a,
                                         uint32_t b0, uint32_t b1) {
    asm volatile(
        "mma.sync.aligned.m16n8k16.row.col.f32.f16.f16.f32 "
        "{%0,%1,%2,%3}, {%4,%5,%6,%7}, {%8,%9}, {%0,%1,%2,%3};"
        : "+f"(c[0]), "+f"(c[1]), "+f"(c[2]), "+f"(c[3])
        : "r"(a[0]), "r"(a[1]), "r"(a[2]), "r"(a[3]), "r"(b0), "r"(b1));
}
__device__ __forceinline__ void cp16(uint32_t dst, const void* src) {
    asm volatile("cp.async.cg.shared.global [%0], [%1], 16;"
                 :: "r"(dst), "l"(src));
}
#define CP_COMMIT() asm volatile("cp.async.commit_group;" ::: "memory")
#define CP_WAIT0()  asm volatile("cp.async.wait_group 0;" ::: "memory")

// ---------------------------------------------------------------------------
// prep kernels
// ---------------------------------------------------------------------------
__global__ void prep_xT(const float* __restrict__ x) {
    __shared__ float s[32][33];
    int f0 = blockIdx.x * 32, b0 = blockIdx.y * 32;
    int tx = threadIdx.x, ty = threadIdx.y;
    #pragma unroll
    for (int i = 0; i < 4; ++i)
        s[ty + 8 * i][tx] = x[(size_t)(b0 + ty + 8 * i) * F_TOTAL + f0 + tx];
    __syncthreads();
    #pragma unroll
    for (int i = 0; i < 4; ++i)
        g_xT[(size_t)(f0 + ty + 8 * i) * B_TOTAL + b0 + tx] = s[tx][ty + 8 * i];
}

// W2[f]: [128 k][64 n] -> f16 records: e = ((half*4+kt)*8+nt)*32+lane
__global__ void prep_w2(const float* __restrict__ W2) {
    __shared__ float s[128 * 64];
    const int f = blockIdx.x, tid = threadIdx.x;
    for (int i = tid; i < 8192; i += 256) s[i] = W2[(size_t)f * 8192 + i];
    __syncthreads();
    for (int e = tid; e < 2048; e += 256) {
        int lane = e & 31, nt = (e >> 5) & 7, kt = (e >> 8) & 3, half = (e >> 10) & 1;
        int g = lane >> 2, tig = lane & 3;
        int n = nt * 8 + g;
        int k0 = half * 64 + kt * 16 + tig * 2;
        uint32_t h0 = packh2(s[k0 * 64 + n],       s[(k0 + 1) * 64 + n]);
        uint32_t h1 = packh2(s[(k0 + 8) * 64 + n], s[(k0 + 9) * 64 + n]);
        g_B2[(size_t)f * 2048 + e] = make_uint2(h0, h1);
    }
}

// W3[f]: [64 k][32 n] -> split records: e = (kt*4+nt)*32+lane
__global__ void prep_w3(const float* __restrict__ W3) {
    __shared__ float s[64 * 32];
    const int f = blockIdx.x, tid = threadIdx.x;
    for (int i = tid; i < 2048; i += 256) s[i] = W3[(size_t)f * 2048 + i];
    __syncthreads();
    for (int e = tid; e < 512; e += 256) {
        int lane = e & 31, nt = (e >> 5) & 3, kt = (e >> 7) & 3;
        int g = lane >> 2, tig = lane & 3;
        int n = nt * 8 + g;
        int k0 = kt * 16 + tig * 2;
        uint32_t h0, l0, h1, l1;
        splith2(s[k0 * 32 + n],       s[(k0 + 1) * 32 + n], h0, l0);
        splith2(s[(k0 + 8) * 32 + n], s[(k0 + 9) * 32 + n], h1, l1);
        g_B3[(size_t)f * 512 + e] = make_uint4(h0, h1, l0, l1);
    }
}

// W1/b1[f]: [128] -> packed f16x2 fragment records: e = (half*4+kt)*32+lane
// record = {w(c,c+1), w(c+8,c+9), b(c,c+1), b(c+8,c+9)}, c = half*64+kt*16+tig*2
__global__ void prep_w1(const float* __restrict__ W1, const float* __restrict__ b1) {
    const int f = blockIdx.x, tid = threadIdx.x;
    if (tid < 256) {
        int lane = tid & 31, kt = (tid >> 5) & 3, half = (tid >> 7) & 1;
        int tig = lane & 3;
        int c = half * 64 + kt * 16 + tig * 2;
        const float* w = W1 + (size_t)f * 128;
        const float* b = b1 + (size_t)f * 128;
        g_WB[(size_t)f * 256 + tid] =
            make_uint4(packh2(w[c], w[c + 1]), packh2(w[c + 8], w[c + 9]),
                       packh2(b[c], b[c + 1]), packh2(b[c + 8], b[c + 9]));
    }
}

// ---------------------------------------------------------------------------
__global__ __launch_bounds__(NTHREADS)
void nam_main(const float* __restrict__ b2, const float* __restrict__ b3,
              const float* __restrict__ W4, const float* __restrict__ b4)
{
    extern __shared__ __align__(16) char smem[];
    const uint32_t sbase = (uint32_t)__cvta_generic_to_shared(smem);

    const int tid = threadIdx.x;
    const int lam = tid & 31;
    const int g = lam >> 2, tig = lam & 3;
    const int row = blockIdx.x * NTHREADS + tid;
    const int f0 = blockIdx.y * FPG;

    // ---- cp.async staging of one feature's records into buffer `buf` ----
    auto stage = [&](int buf, int f) {
        const char* s2 = (const char*)(g_B2 + (size_t)f * 2048);
        uint32_t d2 = sbase + SM_B2 + (uint32_t)buf * 16384u;
        #pragma unroll
        for (int i = 0; i < 8; ++i) {
            int t = tid + i * NTHREADS;
            cp16(d2 + t * 16, s2 + t * 16);
        }
        const char* s3 = (const char*)(g_B3 + (size_t)f * 512);
        uint32_t d3 = sbase + SM_B3 + (uint32_t)buf * 8192u;
        #pragma unroll
        for (int i = 0; i < 4; ++i) {
            int t = tid + i * NTHREADS;
            cp16(d3 + t * 16, s3 + t * 16);
        }
        const char* sw = (const char*)(g_WB + (size_t)f * 256);
        uint32_t dw = sbase + SM_WB + (uint32_t)buf * 4096u;
        #pragma unroll
        for (int i = 0; i < 2; ++i) {
            int t = tid + i * NTHREADS;
            cp16(dw + t * 16, sw + t * 16);
        }
        uint32_t dm = sbase + SM_MISC + (uint32_t)buf * 512u;
        if (tid < 16)
            cp16(dm + tid * 16, b2 + (size_t)f * 64 + tid * 4);
        else if (tid < 24)
            cp16(dm + 256 + (tid - 16) * 16, b3 + (size_t)f * 32 + (tid - 16) * 4);
        else if (tid < 32)
            cp16(dm + 384 + (tid - 24) * 16, W4 + (size_t)f * 32 + (tid - 24) * 4);
    };

    float acc = 0.0f;

    stage(0, f0);
    CP_COMMIT();

    for (int fi = 0; fi < FPG; ++fi) {
        const int f = f0 + fi;
        const int cur = fi & 1;

        const float xv = g_xT[(size_t)f * B_TOTAL + row];   // hoisted LDG

        CP_WAIT0();
        __syncthreads();          // cur buffer ready; prev buffer fully consumed

        if (fi + 1 < FPG) {       // prefetch next feature into the other buffer
            stage(1 - cur, f + 1);
            CP_COMMIT();
        }

        const uint2* sB2 = (const uint2*)(smem + SM_B2) + cur * 2048;
        const uint4* sB3 = (const uint4*)(smem + SM_B3) + cur * 512;
        const uint4* sWB = (const uint4*)(smem + SM_WB) + cur * 256;
        const float* sM  = (const float*)(smem + SM_MISC) + cur * 128;
        const float* sB2v = sM;
        const float* sB3v = sM + 64;
        const float* sW4v = sM + 96;

        // x for this lane's 4 fragment rows (g, g+8, g+16, g+24), dup f16x2
        uint32_t xh[4];
        #pragma unroll
        for (int j = 0; j < 4; ++j) {
            float xx = __shfl_sync(0xffffffffu, xv, g + 8 * j);
            xh[j] = packh2(xx, xx);
        }

        // ---- layer 1 (f16x2 in fragment order) + layer 2 MMA, 1 pass ----
        float acc2[2][8][4] = {};
        #pragma unroll
        for (int half = 0; half < 2; ++half) {
            #pragma unroll
            for (int kt = 0; kt < 4; ++kt) {
                uint4 wb = sWB[(half * 4 + kt) * 32 + lam];
                uint32_t A[2][4];
                #pragma unroll
                for (int mt = 0; mt < 2; ++mt)
                    #pragma unroll
                    for (int i2 = 0; i2 < 2; ++i2) {
                        uint32_t xx = xh[mt * 2 + i2];
                        A[mt][i2]     = hfma2_relu(xx, wb.x, wb.z);
                        A[mt][i2 + 2] = hfma2_relu(xx, wb.y, wb.w);
                    }
                const uint2* bp = sB2 + ((half * 4 + kt) * 8) * 32;
                #pragma unroll
                for (int nt = 0; nt < 8; ++nt) {
                    uint2 B = bp[nt * 32 + lam];
                    #pragma unroll
                    for (int mt = 0; mt < 2; ++mt)
                        mma16816(acc2[mt][nt], A[mt], B.x, B.y);
                }
            }
        }

        // ---- epi2 + layer 3 fused per kt3 (A single, B split -> 2 passes) ----
        float acc3[2][4][4] = {};
        #pragma unroll
        for (int kt3 = 0; kt3 < 4; ++kt3) {
            uint32_t a3[2][4];
            #pragma unroll
            for (int mt = 0; mt < 2; ++mt)
                #pragma unroll
                for (int j = 0; j < 2; ++j) {
                    int nt = kt3 * 2 + j;
                    float2 bv = *(const float2*)(sB2v + nt * 8 + 2 * tig);
                    float v0 = fmaxf(acc2[mt][nt][0] + bv.x, 0.0f);
                    float v1 = fmaxf(acc2[mt][nt][1] + bv.y, 0.0f);
                    float v2 = fmaxf(acc2[mt][nt][2] + bv.x, 0.0f);
                    float v3 = fmaxf(acc2[mt][nt][3] + bv.y, 0.0f);
                    a3[mt][j * 2]     = packh2(v0, v1);
                    a3[mt][j * 2 + 1] = packh2(v2, v3);
                }
            const uint4* bp = sB3 + (kt3 * 4) * 32;
            #pragma unroll
            for (int nt = 0; nt < 4; ++nt) {
                uint4 B = bp[nt * 32 + lam];
                #pragma unroll
                for (int mt = 0; mt < 2; ++mt) {
                    mma16816(acc3[mt][nt], a3[mt], B.x, B.y);   // A*BH
                    mma16816(acc3[mt][nt], a3[mt], B.z, B.w);   // A*BL
                }
            }
        }

        // ---- epi3: +b3, relu, dot W4, warp reduce, distribute ----
        {
            float r0 = 0.f, r1 = 0.f, r2 = 0.f, r3 = 0.f;
            #pragma unroll
            for (int mt = 0; mt < 2; ++mt)
                #pragma unroll
                for (int nt = 0; nt < 4; ++nt) {
                    int col = nt * 8 + tig * 2;
                    float2 b3v = *(const float2*)(sB3v + col);
                    float2 w4v = *(const float2*)(sW4v + col);
                    float lo = fmaxf(acc3[mt][nt][0] + b3v.x, 0.f) * w4v.x
                             + fmaxf(acc3[mt][nt][1] + b3v.y, 0.f) * w4v.y;
                    float hi = fmaxf(acc3[mt][nt][2] + b3v.x, 0.f) * w4v.x
                             + fmaxf(acc3[mt][nt][3] + b3v.y, 0.f) * w4v.y;
                    if (mt == 0) { r0 += lo; r1 += hi; }
                    else         { r2 += lo; r3 += hi; }
                }
            #pragma unroll
            for (int d = 1; d <= 2; d <<= 1) {
                r0 += __shfl_xor_sync(0xffffffffu, r0, d);
                r1 += __shfl_xor_sync(0xffffffffu, r1, d);
                r2 += __shfl_xor_sync(0xffffffffu, r2, d);
                r3 += __shfl_xor_sync(0xffffffffu, r3, d);
            }
            int src = (lam & 7) * 4;
            float t0 = __shfl_sync(0xffffffffu, r0, src);
            float t1 = __shfl_sync(0xffffffffu, r1, src);
            float t2 = __shfl_sync(0xffffffffu, r2, src);
            float t3 = __shfl_sync(0xffffffffu, r3, src);
            int sel = lam >> 3;
            float fout = (sel == 0) ? t0 : (sel == 1) ? t1 : (sel == 2) ? t2 : t3;
            acc += fout + __ldg(b4 + f);
        }
    }

    g_partial[blockIdx.y * B_TOTAL + row] = acc;
}

// ---------------------------------------------------------------------------
__global__ void nam_reduce(const float* __restrict__ bias,
                           float* __restrict__ out)
{
    const int b = blockIdx.x * blockDim.x + threadIdx.x;
    if (b < B_TOTAL) {
        float s = bias[0];
        #pragma unroll
        for (int g2 = 0; g2 < FGROUPS; ++g2)
            s += g_partial[g2 * B_TOTAL + b];
        out[b] = s;
    }
}

// ---------------------------------------------------------------------------
extern "C" void kernel_launch(void* const* d_in, const int* in_sizes, int n_in,
                              void* d_out, int out_size)
{
    (void)in_sizes; (void)n_in; (void)out_size;
    const float* x    = (const float*)d_in[0];
    const float* W1   = (const float*)d_in[1];
    const float* b1   = (const float*)d_in[2];
    const float* W2   = (const float*)d_in[3];
    const float* b2   = (const float*)d_in[4];
    const float* W3   = (const float*)d_in[5];
    const float* b3   = (const float*)d_in[6];
    const float* W4   = (const float*)d_in[7];
    const float* b4   = (const float*)d_in[8];
    const float* bias = (const float*)d_in[9];
    float* out = (float*)d_out;

    cudaFuncSetAttribute(nam_main, cudaFuncAttributeMaxDynamicSharedMemorySize,
                         SMEM_BYTES);

    prep_xT<<<dim3(F_TOTAL / 32, B_TOTAL / 32), dim3(32, 8)>>>(x);
    prep_w2<<<F_TOTAL, 256>>>(W2);
    prep_w3<<<F_TOTAL, 256>>>(W3);
    prep_w1<<<F_TOTAL, 256>>>(W1, b1);

    nam_main<<<dim3(BTILES, FGROUPS), NTHREADS, SMEM_BYTES>>>(b2, b3, W4, b4);
    nam_reduce<<<(B_TOTAL + 255) / 256, 256>>>(bias, out);
}

// round 12
// speedup vs baseline: 23.8118x; 2.0907x over previous
#include <cuda_runtime.h>
#include <cuda_fp16.h>
#include <cstdint>

// ---------------------------------------------------------------------------
// NAM via per-feature 1-D piecewise-linear tabulation.
//   Each feature's MLP g_f(x) is PWL in its scalar input. Build: evaluate
//   g_f on a uniform grid (Delta = 2^-7 over [-8,8], 2049 points used) with
//   the validated f16 mma.sync pipeline (26.6% of the full batch work).
//   Eval: out[b] = bias + sum_f lerp(tab_f, x[b,f])  -- exact off-kink bins.
// ---------------------------------------------------------------------------

#define B_TOTAL 8192
#define F_TOTAL 256
#define NTHREADS 128

// table config (exact power-of-two grid)
#define NB      2048
#define T_LO    (-8.0f)
#define T_IDEL  128.0f          // 1/Delta
#define T_DEL   0.0078125f      // 2^-7
#define TROWS   2176            // 17 row-tiles of 128 (need 2049 points)
#define TBT     17
#define TFG     64
#define TFPG    4

// dynamic smem layout (bytes) for the build kernel
#define SM_B2   0u          // [2][2048] uint2 = 32768
#define SM_B3   32768u      // [2][512] uint4  = 16384
#define SM_WB   49152u      // [2][256] uint4  = 8192
#define SM_MISC 57344u      // [2][128] float  = 1024
#define SMEM_BYTES 58368u

__device__ float g_xT[F_TOTAL * B_TOTAL];                       // 8 MB
__device__ __align__(16) uint2 g_B2[F_TOTAL * 2048];            // 4 MB [f][half][kt][nt][lane]
__device__ __align__(16) uint4 g_B3[F_TOTAL * 512];             // 4 MB [f][kt][nt][lane]
__device__ __align__(16) uint4 g_WB[F_TOTAL * 256];             // 1 MB [f][half*4+kt][lane]
__device__ float  g_tabV[F_TOTAL * TROWS];                      // 2.2 MB
__device__ __align__(8) float2 g_tabD[F_TOTAL * NB];            // 4 MB {V, V_next-V}

// ---- helpers ---------------------------------------------------------------
__device__ __forceinline__ uint32_t packh2(float v0, float v1) {
    uint32_t r;                     // low half = v0, high half = v1
    asm("cvt.rn.f16x2.f32 %0, %1, %2;" : "=r"(r) : "f"(v1), "f"(v0));
    return r;
}
__device__ __forceinline__ void splith2(float v0, float v1,
                                        uint32_t& hi, uint32_t& lo) {
    hi = packh2(v0, v1);
    __half2 h = *(__half2*)&hi;
    float2 r = __half22float2(h);
    lo = packh2(v0 - r.x, v1 - r.y);
}
__device__ __forceinline__ uint32_t hfma2_relu(uint32_t x, uint32_t w, uint32_t b) {
    uint32_t t;
    asm("fma.rn.f16x2 %0, %1, %2, %3;" : "=r"(t) : "r"(x), "r"(w), "r"(b));
    uint32_t z;
    asm("max.f16x2 %0, %1, %2;" : "=r"(z) : "r"(t), "r"(0u));
    return z;
}
__device__ __forceinline__ void mma16816(float* c, const uint32_t* a,
                                         uint32_t b0, uint32_t b1) {
    asm volatile(
        "mma.sync.aligned.m16n8k16.row.col.f32.f16.f16.f32 "
        "{%0,%1,%2,%3}, {%4,%5,%6,%7}, {%8,%9}, {%0,%1,%2,%3};"
        : "+f"(c[0]), "+f"(c[1]), "+f"(c[2]), "+f"(c[3])
        : "r"(a[0]), "r"(a[1]), "r"(a[2]), "r"(a[3]), "r"(b0), "r"(b1));
}
__device__ __forceinline__ void cp16(uint32_t dst, const void* src) {
    asm volatile("cp.async.cg.shared.global [%0], [%1], 16;"
                 :: "r"(dst), "l"(src));
}
#define CP_COMMIT() asm volatile("cp.async.commit_group;" ::: "memory")
#define CP_WAIT0()  asm volatile("cp.async.wait_group 0;" ::: "memory")

// ---------------------------------------------------------------------------
// prep: transpose x (for the eval gather pass)
// ---------------------------------------------------------------------------
__global__ void prep_xT(const float* __restrict__ x) {
    __shared__ float s[32][33];
    int f0 = blockIdx.x * 32, b0 = blockIdx.y * 32;
    int tx = threadIdx.x, ty = threadIdx.y;
    #pragma unroll
    for (int i = 0; i < 4; ++i)
        s[ty + 8 * i][tx] = x[(size_t)(b0 + ty + 8 * i) * F_TOTAL + f0 + tx];
    __syncthreads();
    #pragma unroll
    for (int i = 0; i < 4; ++i)
        g_xT[(size_t)(f0 + ty + 8 * i) * B_TOTAL + b0 + tx] = s[tx][ty + 8 * i];
}

// ---------------------------------------------------------------------------
// prep: all weight fragment records in one kernel. blockIdx.y: 0=W2, 1=W3+W1.
// ---------------------------------------------------------------------------
__global__ void prep_w(const float* __restrict__ W2, const float* __restrict__ W3,
                       const float* __restrict__ W1, const float* __restrict__ b1) {
    __shared__ float s[128 * 64];
    const int f = blockIdx.x, tid = threadIdx.x;

    if (blockIdx.y == 0) {
        // W2[f]: [128 k][64 n] -> f16 records: e = ((half*4+kt)*8+nt)*32+lane
        for (int i = tid; i < 8192; i += 256) s[i] = W2[(size_t)f * 8192 + i];
        __syncthreads();
        for (int e = tid; e < 2048; e += 256) {
            int lane = e & 31, nt = (e >> 5) & 7, kt = (e >> 8) & 3, half = (e >> 10) & 1;
            int g = lane >> 2, tig = lane & 3;
            int n = nt * 8 + g;
            int k0 = half * 64 + kt * 16 + tig * 2;
            uint32_t h0 = packh2(s[k0 * 64 + n],       s[(k0 + 1) * 64 + n]);
            uint32_t h1 = packh2(s[(k0 + 8) * 64 + n], s[(k0 + 9) * 64 + n]);
            g_B2[(size_t)f * 2048 + e] = make_uint2(h0, h1);
        }
    } else {
        // W3[f]: [64 k][32 n] -> split records: e = (kt*4+nt)*32+lane
        for (int i = tid; i < 2048; i += 256) s[i] = W3[(size_t)f * 2048 + i];
        __syncthreads();
        for (int e = tid; e < 512; e += 256) {
            int lane = e & 31, nt = (e >> 5) & 3, kt = (e >> 7) & 3;
            int g = lane >> 2, tig = lane & 3;
            int n = nt * 8 + g;
            int k0 = kt * 16 + tig * 2;
            uint32_t h0, l0, h1, l1;
            splith2(s[k0 * 32 + n],       s[(k0 + 1) * 32 + n], h0, l0);
            splith2(s[(k0 + 8) * 32 + n], s[(k0 + 9) * 32 + n], h1, l1);
            g_B3[(size_t)f * 512 + e] = make_uint4(h0, h1, l0, l1);
        }
        // W1/b1[f] -> packed f16x2 records: e = (half*4+kt)*32+lane
        if (tid < 256) {
            int lane = tid & 31, kt = (tid >> 5) & 3, half = (tid >> 7) & 1;
            int tig = lane & 3;
            int c = half * 64 + kt * 16 + tig * 2;
            const float* w = W1 + (size_t)f * 128;
            const float* b = b1 + (size_t)f * 128;
            g_WB[(size_t)f * 256 + tid] =
                make_uint4(packh2(w[c], w[c + 1]), packh2(w[c + 8], w[c + 9]),
                           packh2(b[c], b[c + 1]), packh2(b[c + 8], b[c + 9]));
        }
    }
}

// ---------------------------------------------------------------------------
// build: evaluate g_f on the uniform grid with the f16 MMA pipeline.
// grid (TBT, TFG), 128 threads; row p -> x = T_LO + p*T_DEL (exact fp32).
// ---------------------------------------------------------------------------
__global__ __launch_bounds__(NTHREADS)
void nam_build(const float* __restrict__ b2, const float* __restrict__ b3,
               const float* __restrict__ W4, const float* __restrict__ b4)
{
    extern __shared__ __align__(16) char smem[];
    const uint32_t sbase = (uint32_t)__cvta_generic_to_shared(smem);

    const int tid = threadIdx.x;
    const int lam = tid & 31;
    const int g = lam >> 2, tig = lam & 3;
    const int row = blockIdx.x * NTHREADS + tid;
    const int f0 = blockIdx.y * TFPG;

    auto stage = [&](int buf, int f) {
        const char* s2 = (const char*)(g_B2 + (size_t)f * 2048);
        uint32_t d2 = sbase + SM_B2 + (uint32_t)buf * 16384u;
        #pragma unroll
        for (int i = 0; i < 8; ++i) {
            int t = tid + i * NTHREADS;
            cp16(d2 + t * 16, s2 + t * 16);
        }
        const char* s3 = (const char*)(g_B3 + (size_t)f * 512);
        uint32_t d3 = sbase + SM_B3 + (uint32_t)buf * 8192u;
        #pragma unroll
        for (int i = 0; i < 4; ++i) {
            int t = tid + i * NTHREADS;
            cp16(d3 + t * 16, s3 + t * 16);
        }
        const char* sw = (const char*)(g_WB + (size_t)f * 256);
        uint32_t dw = sbase + SM_WB + (uint32_t)buf * 4096u;
        #pragma unroll
        for (int i = 0; i < 2; ++i) {
            int t = tid + i * NTHREADS;
            cp16(dw + t * 16, sw + t * 16);
        }
        uint32_t dm = sbase + SM_MISC + (uint32_t)buf * 512u;
        if (tid < 16)
            cp16(dm + tid * 16, b2 + (size_t)f * 64 + tid * 4);
        else if (tid < 24)
            cp16(dm + 256 + (tid - 16) * 16, b3 + (size_t)f * 32 + (tid - 16) * 4);
        else if (tid < 32)
            cp16(dm + 384 + (tid - 24) * 16, W4 + (size_t)f * 32 + (tid - 24) * 4);
    };

    stage(0, f0);
    CP_COMMIT();

    const float xv = T_LO + (float)row * T_DEL;   // exact grid point

    for (int fi = 0; fi < TFPG; ++fi) {
        const int f = f0 + fi;
        const int cur = fi & 1;

        CP_WAIT0();
        __syncthreads();

        if (fi + 1 < TFPG) {
            stage(1 - cur, f + 1);
            CP_COMMIT();
        }

        const uint2* sB2 = (const uint2*)(smem + SM_B2) + cur * 2048;
        const uint4* sB3 = (const uint4*)(smem + SM_B3) + cur * 512;
        const uint4* sWB = (const uint4*)(smem + SM_WB) + cur * 256;
        const float* sM  = (const float*)(smem + SM_MISC) + cur * 128;
        const float* sB2v = sM;
        const float* sB3v = sM + 64;
        const float* sW4v = sM + 96;

        uint32_t xh[4];
        #pragma unroll
        for (int j = 0; j < 4; ++j) {
            float xx = __shfl_sync(0xffffffffu, xv, g + 8 * j);
            xh[j] = packh2(xx, xx);
        }

        // ---- layer 1 (f16x2 in fragment order) + layer 2 MMA, 1 pass ----
        float acc2[2][8][4] = {};
        #pragma unroll
        for (int half = 0; half < 2; ++half) {
            #pragma unroll
            for (int kt = 0; kt < 4; ++kt) {
                uint4 wb = sWB[(half * 4 + kt) * 32 + lam];
                uint32_t A[2][4];
                #pragma unroll
                for (int mt = 0; mt < 2; ++mt)
                    #pragma unroll
                    for (int i2 = 0; i2 < 2; ++i2) {
                        uint32_t xx = xh[mt * 2 + i2];
                        A[mt][i2]     = hfma2_relu(xx, wb.x, wb.z);
                        A[mt][i2 + 2] = hfma2_relu(xx, wb.y, wb.w);
                    }
                const uint2* bp = sB2 + ((half * 4 + kt) * 8) * 32;
                #pragma unroll
                for (int nt = 0; nt < 8; ++nt) {
                    uint2 B = bp[nt * 32 + lam];
                    #pragma unroll
                    for (int mt = 0; mt < 2; ++mt)
                        mma16816(acc2[mt][nt], A[mt], B.x, B.y);
                }
            }
        }

        // ---- epi2 + layer 3 fused per kt3 (A single, B split -> 2 passes) ----
        float acc3[2][4][4] = {};
        #pragma unroll
        for (int kt3 = 0; kt3 < 4; ++kt3) {
            uint32_t a3[2][4];
            #pragma unroll
            for (int mt = 0; mt < 2; ++mt)
                #pragma unroll
                for (int j = 0; j < 2; ++j) {
                    int nt = kt3 * 2 + j;
                    float2 bv = *(const float2*)(sB2v + nt * 8 + 2 * tig);
                    float v0 = fmaxf(acc2[mt][nt][0] + bv.x, 0.0f);
                    float v1 = fmaxf(acc2[mt][nt][1] + bv.y, 0.0f);
                    float v2 = fmaxf(acc2[mt][nt][2] + bv.x, 0.0f);
                    float v3 = fmaxf(acc2[mt][nt][3] + bv.y, 0.0f);
                    a3[mt][j * 2]     = packh2(v0, v1);
                    a3[mt][j * 2 + 1] = packh2(v2, v3);
                }
            const uint4* bp = sB3 + (kt3 * 4) * 32;
            #pragma unroll
            for (int nt = 0; nt < 4; ++nt) {
                uint4 B = bp[nt * 32 + lam];
                #pragma unroll
                for (int mt = 0; mt < 2; ++mt) {
                    mma16816(acc3[mt][nt], a3[mt], B.x, B.y);   // A*BH
                    mma16816(acc3[mt][nt], a3[mt], B.z, B.w);   // A*BL
                }
            }
        }

        // ---- epi3: +b3, relu, dot W4, warp reduce, write table value ----
        {
            float r0 = 0.f, r1 = 0.f, r2 = 0.f, r3 = 0.f;
            #pragma unroll
            for (int mt = 0; mt < 2; ++mt)
                #pragma unroll
                for (int nt = 0; nt < 4; ++nt) {
                    int col = nt * 8 + tig * 2;
                    float2 b3v = *(const float2*)(sB3v + col);
                    float2 w4v = *(const float2*)(sW4v + col);
                    float lo = fmaxf(acc3[mt][nt][0] + b3v.x, 0.f) * w4v.x
                             + fmaxf(acc3[mt][nt][1] + b3v.y, 0.f) * w4v.y;
                    float hi = fmaxf(acc3[mt][nt][2] + b3v.x, 0.f) * w4v.x
                             + fmaxf(acc3[mt][nt][3] + b3v.y, 0.f) * w4v.y;
                    if (mt == 0) { r0 += lo; r1 += hi; }
                    else         { r2 += lo; r3 += hi; }
                }
            #pragma unroll
            for (int d = 1; d <= 2; d <<= 1) {
                r0 += __shfl_xor_sync(0xffffffffu, r0, d);
                r1 += __shfl_xor_sync(0xffffffffu, r1, d);
                r2 += __shfl_xor_sync(0xffffffffu, r2, d);
                r3 += __shfl_xor_sync(0xffffffffu, r3, d);
            }
            int src = (lam & 7) * 4;
            float t0 = __shfl_sync(0xffffffffu, r0, src);
            float t1 = __shfl_sync(0xffffffffu, r1, src);
            float t2 = __shfl_sync(0xffffffffu, r2, src);
            float t3 = __shfl_sync(0xffffffffu, r3, src);
            int sel = lam >> 3;
            float fout = (sel == 0) ? t0 : (sel == 1) ? t1 : (sel == 2) ? t2 : t3;
            g_tabV[(size_t)f * TROWS + row] = fout + __ldg(b4 + f);
        }
    }
}

// ---------------------------------------------------------------------------
// pack: tabD[f][i] = {V[i], V[i+1]-V[i]}
// ---------------------------------------------------------------------------
__global__ void nam_pack() {
    int idx = blockIdx.x * blockDim.x + threadIdx.x;   // 256*2048 total
    if (idx < F_TOTAL * NB) {
        int f = idx >> 11, i = idx & (NB - 1);
        float v0 = g_tabV[(size_t)f * TROWS + i];
        float v1 = g_tabV[(size_t)f * TROWS + i + 1];
        g_tabD[idx] = make_float2(v0, v1 - v0);
    }
}

// ---------------------------------------------------------------------------
// eval: out[b] = bias + sum_f lerp(tab_f, x[b,f]).
// block = 256 threads: 64 rows x 4 feature-chunks; deterministic sums.
// ---------------------------------------------------------------------------
__global__ __launch_bounds__(256)
void nam_eval(const float* __restrict__ bias, float* __restrict__ out)
{
    __shared__ float s[4][64];
    const int tid = threadIdx.x;
    const int rloc = tid & 63, chunk = tid >> 6;
    const int b = blockIdx.x * 64 + rloc;
    const int fb = chunk * 64;

    float a0 = 0.f, a1 = 0.f, a2 = 0.f, a3 = 0.f;
    #pragma unroll 4
    for (int j = 0; j < 64; j += 4) {
        #pragma unroll
        for (int q = 0; q < 4; ++q) {
            int f = fb + j + q;
            float xv = g_xT[(size_t)f * B_TOTAL + b];
            float u = fmaf(xv, T_IDEL, 1024.0f);       // (x - T_LO) / Delta
            int i = __float2int_rd(u);
            i = min(max(i, 0), NB - 1);
            float frac = u - (float)i;
            float2 vd = g_tabD[(size_t)f * NB + i];
            float y = fmaf(frac, vd.y, vd.x);
            if (q == 0) a0 += y; else if (q == 1) a1 += y;
            else if (q == 2) a2 += y; else a3 += y;
        }
    }
    s[chunk][rloc] = (a0 + a1) + (a2 + a3);
    __syncthreads();
    if (tid < 64)
        out[b - rloc + tid] = bias[0] +
            ((s[0][tid] + s[1][tid]) + (s[2][tid] + s[3][tid]));
}

// ---------------------------------------------------------------------------
extern "C" void kernel_launch(void* const* d_in, const int* in_sizes, int n_in,
                              void* d_out, int out_size)
{
    (void)in_sizes; (void)n_in; (void)out_size;
    const float* x    = (const float*)d_in[0];
    const float* W1   = (const float*)d_in[1];
    const float* b1   = (const float*)d_in[2];
    const float* W2   = (const float*)d_in[3];
    const float* b2   = (const float*)d_in[4];
    const float* W3   = (const float*)d_in[5];
    const float* b3   = (const float*)d_in[6];
    const float* W4   = (const float*)d_in[7];
    const float* b4   = (const float*)d_in[8];
    const float* bias = (const float*)d_in[9];
    float* out = (float*)d_out;

    cudaFuncSetAttribute(nam_build, cudaFuncAttributeMaxDynamicSharedMemorySize,
                         SMEM_BYTES);

    prep_xT<<<dim3(F_TOTAL / 32, B_TOTAL / 32), dim3(32, 8)>>>(x);
    prep_w<<<dim3(F_TOTAL, 2), 256>>>(W2, W3, W1, b1);

    nam_build<<<dim3(TBT, TFG), NTHREADS, SMEM_BYTES>>>(b2, b3, W4, b4);
    nam_pack<<<(F_TOTAL * NB + 255) / 256, 256>>>();
    nam_eval<<<B_TOTAL / 64, 256>>>(bias, out);
}

// round 13
// speedup vs baseline: 34.8559x; 1.4638x over previous
#include <cuda_runtime.h>
#include <cuda_fp16.h>
#include <cstdint>

// ---------------------------------------------------------------------------
// NAM via per-feature 1-D piecewise-linear tabulation (v2).
//   Build: evaluate g_f on a uniform grid (Delta = 2^-6 over [-8,8], 1025
//   points) with the validated f16 mma.sync pipeline.
//   Eval: out[b] = bias + sum_f lerp(tab_f, x[b,f]); x staged via SMEM
//   transpose inside eval (prep_xT eliminated).
// ---------------------------------------------------------------------------

#define B_TOTAL 8192
#define F_TOTAL 256
#define NTHREADS 128

// table config (exact power-of-two grid)
#define NB      1024
#define T_LO    (-8.0f)
#define T_IDEL  64.0f           // 1/Delta
#define T_DEL   0.015625f       // 2^-6
#define T_OFS   512.0f          // -T_LO * T_IDEL
#define TROWS   1152            // 9 row-tiles of 128 (need 1025 points)
#define TBT     9
#define TFG     128
#define TFPG    2

// dynamic smem layout (bytes) for the build kernel
#define SM_B2   0u          // [2][2048] uint2 = 32768
#define SM_B3   32768u      // [2][512] uint4  = 16384
#define SM_WB   49152u      // [2][256] uint4  = 8192
#define SM_MISC 57344u      // [2][128] float  = 1024
#define SMEM_BYTES 58368u

// eval smem: x slab transposed [256][65] floats
#define EV_STRIDE 65
#define EV_SMEM   (F_TOTAL * EV_STRIDE * 4)   // 66560 bytes

__device__ __align__(16) uint2 g_B2[F_TOTAL * 2048];            // 4 MB [f][half][kt][nt][lane]
__device__ __align__(16) uint4 g_B3[F_TOTAL * 512];             // 4 MB [f][kt][nt][lane]
__device__ __align__(16) uint4 g_WB[F_TOTAL * 256];             // 1 MB [f][half*4+kt][lane]
__device__ float  g_tabV[F_TOTAL * TROWS];                      // 1.2 MB
__device__ __align__(8) float2 g_tabD[F_TOTAL * NB];            // 2 MB {V, V_next-V}

// ---- helpers ---------------------------------------------------------------
__device__ __forceinline__ uint32_t packh2(float v0, float v1) {
    uint32_t r;                     // low half = v0, high half = v1
    asm("cvt.rn.f16x2.f32 %0, %1, %2;" : "=r"(r) : "f"(v1), "f"(v0));
    return r;
}
__device__ __forceinline__ void splith2(float v0, float v1,
                                        uint32_t& hi, uint32_t& lo) {
    hi = packh2(v0, v1);
    __half2 h = *(__half2*)&hi;
    float2 r = __half22float2(h);
    lo = packh2(v0 - r.x, v1 - r.y);
}
__device__ __forceinline__ uint32_t hfma2_relu(uint32_t x, uint32_t w, uint32_t b) {
    uint32_t t;
    asm("fma.rn.f16x2 %0, %1, %2, %3;" : "=r"(t) : "r"(x), "r"(w), "r"(b));
    uint32_t z;
    asm("max.f16x2 %0, %1, %2;" : "=r"(z) : "r"(t), "r"(0u));
    return z;
}
__device__ __forceinline__ void mma16816(float* c, const uint32_t* a,
                                         uint32_t b0, uint32_t b1) {
    asm volatile(
        "mma.sync.aligned.m16n8k16.row.col.f32.f16.f16.f32 "
        "{%0,%1,%2,%3}, {%4,%5,%6,%7}, {%8,%9}, {%0,%1,%2,%3};"
        : "+f"(c[0]), "+f"(c[1]), "+f"(c[2]), "+f"(c[3])
        : "r"(a[0]), "r"(a[1]), "r"(a[2]), "r"(a[3]), "r"(b0), "r"(b1));
}
__device__ __forceinline__ void cp16(uint32_t dst, const void* src) {
    asm volatile("cp.async.cg.shared.global [%0], [%1], 16;"
                 :: "r"(dst), "l"(src));
}
#define CP_COMMIT() asm volatile("cp.async.commit_group;" ::: "memory")
#define CP_WAIT0()  asm volatile("cp.async.wait_group 0;" ::: "memory")

// ---------------------------------------------------------------------------
// prep: all weight fragment records in one kernel. blockIdx.y: 0=W2, 1=W3+W1.
// ---------------------------------------------------------------------------
__global__ void prep_w(const float* __restrict__ W2, const float* __restrict__ W3,
                       const float* __restrict__ W1, const float* __restrict__ b1) {
    __shared__ float s[128 * 64];
    const int f = blockIdx.x, tid = threadIdx.x;

    if (blockIdx.y == 0) {
        // W2[f]: [128 k][64 n] -> f16 records: e = ((half*4+kt)*8+nt)*32+lane
        for (int i = tid; i < 8192; i += 256) s[i] = W2[(size_t)f * 8192 + i];
        __syncthreads();
        for (int e = tid; e < 2048; e += 256) {
            int lane = e & 31, nt = (e >> 5) & 7, kt = (e >> 8) & 3, half = (e >> 10) & 1;
            int g = lane >> 2, tig = lane & 3;
            int n = nt * 8 + g;
            int k0 = half * 64 + kt * 16 + tig * 2;
            uint32_t h0 = packh2(s[k0 * 64 + n],       s[(k0 + 1) * 64 + n]);
            uint32_t h1 = packh2(s[(k0 + 8) * 64 + n], s[(k0 + 9) * 64 + n]);
            g_B2[(size_t)f * 2048 + e] = make_uint2(h0, h1);
        }
    } else {
        // W3[f]: [64 k][32 n] -> split records: e = (kt*4+nt)*32+lane
        for (int i = tid; i < 2048; i += 256) s[i] = W3[(size_t)f * 2048 + i];
        __syncthreads();
        for (int e = tid; e < 512; e += 256) {
            int lane = e & 31, nt = (e >> 5) & 3, kt = (e >> 7) & 3;
            int g = lane >> 2, tig = lane & 3;
            int n = nt * 8 + g;
            int k0 = kt * 16 + tig * 2;
            uint32_t h0, l0, h1, l1;
            splith2(s[k0 * 32 + n],       s[(k0 + 1) * 32 + n], h0, l0);
            splith2(s[(k0 + 8) * 32 + n], s[(k0 + 9) * 32 + n], h1, l1);
            g_B3[(size_t)f * 512 + e] = make_uint4(h0, h1, l0, l1);
        }
        // W1/b1[f] -> packed f16x2 records: e = (half*4+kt)*32+lane
        if (tid < 256) {
            int lane = tid & 31, kt = (tid >> 5) & 3, half = (tid >> 7) & 1;
            int tig = lane & 3;
            int c = half * 64 + kt * 16 + tig * 2;
            const float* w = W1 + (size_t)f * 128;
            const float* b = b1 + (size_t)f * 128;
            g_WB[(size_t)f * 256 + tid] =
                make_uint4(packh2(w[c], w[c + 1]), packh2(w[c + 8], w[c + 9]),
                           packh2(b[c], b[c + 1]), packh2(b[c + 8], b[c + 9]));
        }
    }
}

// ---------------------------------------------------------------------------
// build: evaluate g_f on the uniform grid with the f16 MMA pipeline.
// grid (TBT, TFG), 128 threads; row p -> x = T_LO + p*T_DEL (exact fp32).
// ---------------------------------------------------------------------------
__global__ __launch_bounds__(NTHREADS)
void nam_build(const float* __restrict__ b2, const float* __restrict__ b3,
               const float* __restrict__ W4, const float* __restrict__ b4)
{
    extern __shared__ __align__(16) char smem[];
    const uint32_t sbase = (uint32_t)__cvta_generic_to_shared(smem);

    const int tid = threadIdx.x;
    const int lam = tid & 31;
    const int g = lam >> 2, tig = lam & 3;
    const int row = blockIdx.x * NTHREADS + tid;
    const int f0 = blockIdx.y * TFPG;

    auto stage = [&](int buf, int f) {
        const char* s2 = (const char*)(g_B2 + (size_t)f * 2048);
        uint32_t d2 = sbase + SM_B2 + (uint32_t)buf * 16384u;
        #pragma unroll
        for (int i = 0; i < 8; ++i) {
            int t = tid + i * NTHREADS;
            cp16(d2 + t * 16, s2 + t * 16);
        }
        const char* s3 = (const char*)(g_B3 + (size_t)f * 512);
        uint32_t d3 = sbase + SM_B3 + (uint32_t)buf * 8192u;
        #pragma unroll
        for (int i = 0; i < 4; ++i) {
            int t = tid + i * NTHREADS;
            cp16(d3 + t * 16, s3 + t * 16);
        }
        const char* sw = (const char*)(g_WB + (size_t)f * 256);
        uint32_t dw = sbase + SM_WB + (uint32_t)buf * 4096u;
        #pragma unroll
        for (int i = 0; i < 2; ++i) {
            int t = tid + i * NTHREADS;
            cp16(dw + t * 16, sw + t * 16);
        }
        uint32_t dm = sbase + SM_MISC + (uint32_t)buf * 512u;
        if (tid < 16)
            cp16(dm + tid * 16, b2 + (size_t)f * 64 + tid * 4);
        else if (tid < 24)
            cp16(dm + 256 + (tid - 16) * 16, b3 + (size_t)f * 32 + (tid - 16) * 4);
        else if (tid < 32)
            cp16(dm + 384 + (tid - 24) * 16, W4 + (size_t)f * 32 + (tid - 24) * 4);
    };

    stage(0, f0);
    CP_COMMIT();

    const float xv = T_LO + (float)row * T_DEL;   // exact grid point

    for (int fi = 0; fi < TFPG; ++fi) {
        const int f = f0 + fi;
        const int cur = fi & 1;

        CP_WAIT0();
        __syncthreads();

        if (fi + 1 < TFPG) {
            stage(1 - cur, f + 1);
            CP_COMMIT();
        }

        const uint2* sB2 = (const uint2*)(smem + SM_B2) + cur * 2048;
        const uint4* sB3 = (const uint4*)(smem + SM_B3) + cur * 512;
        const uint4* sWB = (const uint4*)(smem + SM_WB) + cur * 256;
        const float* sM  = (const float*)(smem + SM_MISC) + cur * 128;
        const float* sB2v = sM;
        const float* sB3v = sM + 64;
        const float* sW4v = sM + 96;

        uint32_t xh[4];
        #pragma unroll
        for (int j = 0; j < 4; ++j) {
            float xx = __shfl_sync(0xffffffffu, xv, g + 8 * j);
            xh[j] = packh2(xx, xx);
        }

        // ---- layer 1 (f16x2 in fragment order) + layer 2 MMA, 1 pass ----
        float acc2[2][8][4] = {};
        #pragma unroll
        for (int half = 0; half < 2; ++half) {
            #pragma unroll
            for (int kt = 0; kt < 4; ++kt) {
                uint4 wb = sWB[(half * 4 + kt) * 32 + lam];
                uint32_t A[2][4];
                #pragma unroll
                for (int mt = 0; mt < 2; ++mt)
                    #pragma unroll
                    for (int i2 = 0; i2 < 2; ++i2) {
                        uint32_t xx = xh[mt * 2 + i2];
                        A[mt][i2]     = hfma2_relu(xx, wb.x, wb.z);
                        A[mt][i2 + 2] = hfma2_relu(xx, wb.y, wb.w);
                    }
                const uint2* bp = sB2 + ((half * 4 + kt) * 8) * 32;
                #pragma unroll
                for (int nt = 0; nt < 8; ++nt) {
                    uint2 B = bp[nt * 32 + lam];
                    #pragma unroll
                    for (int mt = 0; mt < 2; ++mt)
                        mma16816(acc2[mt][nt], A[mt], B.x, B.y);
                }
            }
        }

        // ---- epi2 + layer 3 fused per kt3 (A single, B split -> 2 passes) ----
        float acc3[2][4][4] = {};
        #pragma unroll
        for (int kt3 = 0; kt3 < 4; ++kt3) {
            uint32_t a3[2][4];
            #pragma unroll
            for (int mt = 0; mt < 2; ++mt)
                #pragma unroll
                for (int j = 0; j < 2; ++j) {
                    int nt = kt3 * 2 + j;
                    float2 bv = *(const float2*)(sB2v + nt * 8 + 2 * tig);
                    float v0 = fmaxf(acc2[mt][nt][0] + bv.x, 0.0f);
                    float v1 = fmaxf(acc2[mt][nt][1] + bv.y, 0.0f);
                    float v2 = fmaxf(acc2[mt][nt][2] + bv.x, 0.0f);
                    float v3 = fmaxf(acc2[mt][nt][3] + bv.y, 0.0f);
                    a3[mt][j * 2]     = packh2(v0, v1);
                    a3[mt][j * 2 + 1] = packh2(v2, v3);
                }
            const uint4* bp = sB3 + (kt3 * 4) * 32;
            #pragma unroll
            for (int nt = 0; nt < 4; ++nt) {
                uint4 B = bp[nt * 32 + lam];
                #pragma unroll
                for (int mt = 0; mt < 2; ++mt) {
                    mma16816(acc3[mt][nt], a3[mt], B.x, B.y);   // A*BH
                    mma16816(acc3[mt][nt], a3[mt], B.z, B.w);   // A*BL
                }
            }
        }

        // ---- epi3: +b3, relu, dot W4, warp reduce, write table value ----
        {
            float r0 = 0.f, r1 = 0.f, r2 = 0.f, r3 = 0.f;
            #pragma unroll
            for (int mt = 0; mt < 2; ++mt)
                #pragma unroll
                for (int nt = 0; nt < 4; ++nt) {
                    int col = nt * 8 + tig * 2;
                    float2 b3v = *(const float2*)(sB3v + col);
                    float2 w4v = *(const float2*)(sW4v + col);
                    float lo = fmaxf(acc3[mt][nt][0] + b3v.x, 0.f) * w4v.x
                             + fmaxf(acc3[mt][nt][1] + b3v.y, 0.f) * w4v.y;
                    float hi = fmaxf(acc3[mt][nt][2] + b3v.x, 0.f) * w4v.x
                             + fmaxf(acc3[mt][nt][3] + b3v.y, 0.f) * w4v.y;
                    if (mt == 0) { r0 += lo; r1 += hi; }
                    else         { r2 += lo; r3 += hi; }
                }
            #pragma unroll
            for (int d = 1; d <= 2; d <<= 1) {
                r0 += __shfl_xor_sync(0xffffffffu, r0, d);
                r1 += __shfl_xor_sync(0xffffffffu, r1, d);
                r2 += __shfl_xor_sync(0xffffffffu, r2, d);
                r3 += __shfl_xor_sync(0xffffffffu, r3, d);
            }
            int src = (lam & 7) * 4;
            float t0 = __shfl_sync(0xffffffffu, r0, src);
            float t1 = __shfl_sync(0xffffffffu, r1, src);
            float t2 = __shfl_sync(0xffffffffu, r2, src);
            float t3 = __shfl_sync(0xffffffffu, r3, src);
            int sel = lam >> 3;
            float fout = (sel == 0) ? t0 : (sel == 1) ? t1 : (sel == 2) ? t2 : t3;
            g_tabV[(size_t)f * TROWS + row] = fout + __ldg(b4 + f);
        }
    }
}

// ---------------------------------------------------------------------------
// pack: tabD[f][i] = {V[i], V[i+1]-V[i]}
// ---------------------------------------------------------------------------
__global__ void nam_pack() {
    int idx = blockIdx.x * blockDim.x + threadIdx.x;   // 256*1024 total
    if (idx < F_TOTAL * NB) {
        int f = idx >> 10, i = idx & (NB - 1);
        float v0 = g_tabV[(size_t)f * TROWS + i];
        float v1 = g_tabV[(size_t)f * TROWS + i + 1];
        g_tabD[idx] = make_float2(v0, v1 - v0);
    }
}

// ---------------------------------------------------------------------------
// eval: out[b] = bias + sum_f lerp(tab_f, x[b,f]).
// Block = 256 threads, 64 batch rows. x slab loaded coalesced and transposed
// into smem [f][r] (stride 65, conflict-free reads). Deterministic sums.
// ---------------------------------------------------------------------------
__global__ __launch_bounds__(256)
void nam_eval(const float* __restrict__ x, const float* __restrict__ bias,
              float* __restrict__ out)
{
    extern __shared__ float sX[];                  // [256][65]
    __shared__ float sred[4][64];
    const int tid = threadIdx.x;
    const int b0 = blockIdx.x * 64;

    // coalesced load + smem transpose: 4096 float4 = 16 per thread
    #pragma unroll
    for (int i = 0; i < 16; ++i) {
        int idx4 = tid + i * 256;                  // float4 index
        int r = idx4 >> 6, c4 = idx4 & 63;
        float4 v = ((const float4*)(x + (size_t)(b0 + r) * F_TOTAL))[c4];
        int f = c4 * 4;
        sX[(f + 0) * EV_STRIDE + r] = v.x;
        sX[(f + 1) * EV_STRIDE + r] = v.y;
        sX[(f + 2) * EV_STRIDE + r] = v.z;
        sX[(f + 3) * EV_STRIDE + r] = v.w;
    }
    __syncthreads();

    const int rloc = tid & 63, chunk = tid >> 6;
    const int fb = chunk * 64;
    const int b = b0 + rloc;

    float a0 = 0.f, a1 = 0.f, a2 = 0.f, a3 = 0.f;
    #pragma unroll 4
    for (int j = 0; j < 64; j += 4) {
        #pragma unroll
        for (int q = 0; q < 4; ++q) {
            int f = fb + j + q;
            float xv = sX[f * EV_STRIDE + rloc];
            float u = fmaf(xv, T_IDEL, T_OFS);     // (x - T_LO) / Delta
            int i = __float2int_rd(u);
            i = min(max(i, 0), NB - 1);
            float frac = u - (float)i;
            float2 vd = g_tabD[(size_t)f * NB + i];
            float y = fmaf(frac, vd.y, vd.x);
            if (q == 0) a0 += y; else if (q == 1) a1 += y;
            else if (q == 2) a2 += y; else a3 += y;
        }
    }
    sred[chunk][rloc] = (a0 + a1) + (a2 + a3);
    __syncthreads();
    if (tid < 64)
        out[b0 + tid] = bias[0] +
            ((sred[0][tid] + sred[1][tid]) + (sred[2][tid] + sred[3][tid]));
}

// ---------------------------------------------------------------------------
extern "C" void kernel_launch(void* const* d_in, const int* in_sizes, int n_in,
                              void* d_out, int out_size)
{
    (void)in_sizes; (void)n_in; (void)out_size;
    const float* x    = (const float*)d_in[0];
    const float* W1   = (const float*)d_in[1];
    const float* b1   = (const float*)d_in[2];
    const float* W2   = (const float*)d_in[3];
    const float* b2   = (const float*)d_in[4];
    const float* W3   = (const float*)d_in[5];
    const float* b3   = (const float*)d_in[6];
    const float* W4   = (const float*)d_in[7];
    const float* b4   = (const float*)d_in[8];
    const float* bias = (const float*)d_in[9];
    float* out = (float*)d_out;

    cudaFuncSetAttribute(nam_build, cudaFuncAttributeMaxDynamicSharedMemorySize,
                         SMEM_BYTES);
    cudaFuncSetAttribute(nam_eval, cudaFuncAttributeMaxDynamicSharedMemorySize,
                         EV_SMEM);

    prep_w<<<dim3(F_TOTAL, 2), 256>>>(W2, W3, W1, b1);
    nam_build<<<dim3(TBT, TFG), NTHREADS, SMEM_BYTES>>>(b2, b3, W4, b4);
    nam_pack<<<(F_TOTAL * NB + 255) / 256, 256>>>();
    nam_eval<<<B_TOTAL / 64, 256, EV_SMEM>>>(x, bias, out);
}

// round 14
// speedup vs baseline: 55.2954x; 1.5864x over previous
#include <cuda_runtime.h>
#include <cuda_fp16.h>
#include <cstdint>

// ---------------------------------------------------------------------------
// NAM via per-feature 1-D piecewise-linear tabulation (v3).
//   Build: evaluate g_f on a uniform grid (Delta = 2^-5 over [-8,8], 513
//   points used) with the validated f16 mma.sync pipeline.
//   Eval: out[b] = bias + sum_f lerp(tabV_f, x[b,f]); 512 blocks x 16 rows,
//   16 gathers/thread, slope formed inline (pack kernel eliminated).
// ---------------------------------------------------------------------------

#define B_TOTAL 8192
#define F_TOTAL 256
#define NTHREADS 128

// table config (exact power-of-two grid)
#define NB      512
#define T_LO    (-8.0f)
#define T_IDEL  32.0f           // 1/Delta
#define T_DEL   0.03125f        // 2^-5
#define T_OFS   256.0f          // -T_LO * T_IDEL
#define TROWS   640             // 5 row-tiles of 128 (need 513 points)
#define TBT     5
#define TFG     128
#define TFPG    2

// dynamic smem layout (bytes) for the build kernel
#define SM_B2   0u          // [2][2048] uint2 = 32768
#define SM_B3   32768u      // [2][512] uint4  = 16384
#define SM_WB   49152u      // [2][256] uint4  = 8192
#define SM_MISC 57344u      // [2][128] float  = 1024
#define SMEM_BYTES 58368u

// eval config
#define EV_ROWS   16
#define EV_STRIDE 17

__device__ __align__(16) uint2 g_B2[F_TOTAL * 2048];            // 4 MB [f][half][kt][nt][lane]
__device__ __align__(16) uint4 g_B3[F_TOTAL * 512];             // 4 MB [f][kt][nt][lane]
__device__ __align__(16) uint4 g_WB[F_TOTAL * 256];             // 1 MB [f][half*4+kt][lane]
__device__ float  g_tabV[F_TOTAL * TROWS];                      // 640 KB

// ---- helpers ---------------------------------------------------------------
__device__ __forceinline__ uint32_t packh2(float v0, float v1) {
    uint32_t r;                     // low half = v0, high half = v1
    asm("cvt.rn.f16x2.f32 %0, %1, %2;" : "=r"(r) : "f"(v1), "f"(v0));
    return r;
}
__device__ __forceinline__ void splith2(float v0, float v1,
                                        uint32_t& hi, uint32_t& lo) {
    hi = packh2(v0, v1);
    __half2 h = *(__half2*)&hi;
    float2 r = __half22float2(h);
    lo = packh2(v0 - r.x, v1 - r.y);
}
__device__ __forceinline__ uint32_t hfma2_relu(uint32_t x, uint32_t w, uint32_t b) {
    uint32_t t;
    asm("fma.rn.f16x2 %0, %1, %2, %3;" : "=r"(t) : "r"(x), "r"(w), "r"(b));
    uint32_t z;
    asm("max.f16x2 %0, %1, %2;" : "=r"(z) : "r"(t), "r"(0u));
    return z;
}
__device__ __forceinline__ void mma16816(float* c, const uint32_t* a,
                                         uint32_t b0, uint32_t b1) {
    asm volatile(
        "mma.sync.aligned.m16n8k16.row.col.f32.f16.f16.f32 "
        "{%0,%1,%2,%3}, {%4,%5,%6,%7}, {%8,%9}, {%0,%1,%2,%3};"
        : "+f"(c[0]), "+f"(c[1]), "+f"(c[2]), "+f"(c[3])
        : "r"(a[0]), "r"(a[1]), "r"(a[2]), "r"(a[3]), "r"(b0), "r"(b1));
}
__device__ __forceinline__ void cp16(uint32_t dst, const void* src) {
    asm volatile("cp.async.cg.shared.global [%0], [%1], 16;"
                 :: "r"(dst), "l"(src));
}
#define CP_COMMIT() asm volatile("cp.async.commit_group;" ::: "memory")
#define CP_WAIT0()  asm volatile("cp.async.wait_group 0;" ::: "memory")

// ---------------------------------------------------------------------------
// prep: all weight fragment records in one kernel. blockIdx.y: 0=W2, 1=W3+W1.
// ---------------------------------------------------------------------------
__global__ void prep_w(const float* __restrict__ W2, const float* __restrict__ W3,
                       const float* __restrict__ W1, const float* __restrict__ b1) {
    __shared__ float s[128 * 64];
    const int f = blockIdx.x, tid = threadIdx.x;

    if (blockIdx.y == 0) {
        // W2[f]: [128 k][64 n] -> f16 records: e = ((half*4+kt)*8+nt)*32+lane
        for (int i = tid; i < 8192; i += 256) s[i] = W2[(size_t)f * 8192 + i];
        __syncthreads();
        for (int e = tid; e < 2048; e += 256) {
            int lane = e & 31, nt = (e >> 5) & 7, kt = (e >> 8) & 3, half = (e >> 10) & 1;
            int g = lane >> 2, tig = lane & 3;
            int n = nt * 8 + g;
            int k0 = half * 64 + kt * 16 + tig * 2;
            uint32_t h0 = packh2(s[k0 * 64 + n],       s[(k0 + 1) * 64 + n]);
            uint32_t h1 = packh2(s[(k0 + 8) * 64 + n], s[(k0 + 9) * 64 + n]);
            g_B2[(size_t)f * 2048 + e] = make_uint2(h0, h1);
        }
    } else {
        // W3[f]: [64 k][32 n] -> split records: e = (kt*4+nt)*32+lane
        for (int i = tid; i < 2048; i += 256) s[i] = W3[(size_t)f * 2048 + i];
        __syncthreads();
        for (int e = tid; e < 512; e += 256) {
            int lane = e & 31, nt = (e >> 5) & 3, kt = (e >> 7) & 3;
            int g = lane >> 2, tig = lane & 3;
            int n = nt * 8 + g;
            int k0 = kt * 16 + tig * 2;
            uint32_t h0, l0, h1, l1;
            splith2(s[k0 * 32 + n],       s[(k0 + 1) * 32 + n], h0, l0);
            splith2(s[(k0 + 8) * 32 + n], s[(k0 + 9) * 32 + n], h1, l1);
            g_B3[(size_t)f * 512 + e] = make_uint4(h0, h1, l0, l1);
        }
        // W1/b1[f] -> packed f16x2 records: e = (half*4+kt)*32+lane
        if (tid < 256) {
            int lane = tid & 31, kt = (tid >> 5) & 3, half = (tid >> 7) & 1;
            int tig = lane & 3;
            int c = half * 64 + kt * 16 + tig * 2;
            const float* w = W1 + (size_t)f * 128;
            const float* b = b1 + (size_t)f * 128;
            g_WB[(size_t)f * 256 + tid] =
                make_uint4(packh2(w[c], w[c + 1]), packh2(w[c + 8], w[c + 9]),
                           packh2(b[c], b[c + 1]), packh2(b[c + 8], b[c + 9]));
        }
    }
}

// ---------------------------------------------------------------------------
// build: evaluate g_f on the uniform grid with the f16 MMA pipeline.
// grid (TBT, TFG), 128 threads; row p -> x = T_LO + p*T_DEL (exact fp32).
// ---------------------------------------------------------------------------
__global__ __launch_bounds__(NTHREADS)
void nam_build(const float* __restrict__ b2, const float* __restrict__ b3,
               const float* __restrict__ W4, const float* __restrict__ b4)
{
    extern __shared__ __align__(16) char smem[];
    const uint32_t sbase = (uint32_t)__cvta_generic_to_shared(smem);

    const int tid = threadIdx.x;
    const int lam = tid & 31;
    const int g = lam >> 2, tig = lam & 3;
    const int row = blockIdx.x * NTHREADS + tid;
    const int f0 = blockIdx.y * TFPG;

    auto stage = [&](int buf, int f) {
        const char* s2 = (const char*)(g_B2 + (size_t)f * 2048);
        uint32_t d2 = sbase + SM_B2 + (uint32_t)buf * 16384u;
        #pragma unroll
        for (int i = 0; i < 8; ++i) {
            int t = tid + i * NTHREADS;
            cp16(d2 + t * 16, s2 + t * 16);
        }
        const char* s3 = (const char*)(g_B3 + (size_t)f * 512);
        uint32_t d3 = sbase + SM_B3 + (uint32_t)buf * 8192u;
        #pragma unroll
        for (int i = 0; i < 4; ++i) {
            int t = tid + i * NTHREADS;
            cp16(d3 + t * 16, s3 + t * 16);
        }
        const char* sw = (const char*)(g_WB + (size_t)f * 256);
        uint32_t dw = sbase + SM_WB + (uint32_t)buf * 4096u;
        #pragma unroll
        for (int i = 0; i < 2; ++i) {
            int t = tid + i * NTHREADS;
            cp16(dw + t * 16, sw + t * 16);
        }
        uint32_t dm = sbase + SM_MISC + (uint32_t)buf * 512u;
        if (tid < 16)
            cp16(dm + tid * 16, b2 + (size_t)f * 64 + tid * 4);
        else if (tid < 24)
            cp16(dm + 256 + (tid - 16) * 16, b3 + (size_t)f * 32 + (tid - 16) * 4);
        else if (tid < 32)
            cp16(dm + 384 + (tid - 24) * 16, W4 + (size_t)f * 32 + (tid - 24) * 4);
    };

    stage(0, f0);
    CP_COMMIT();

    const float xv = T_LO + (float)row * T_DEL;   // exact grid point

    for (int fi = 0; fi < TFPG; ++fi) {
        const int f = f0 + fi;
        const int cur = fi & 1;

        CP_WAIT0();
        __syncthreads();

        if (fi + 1 < TFPG) {
            stage(1 - cur, f + 1);
            CP_COMMIT();
        }

        const uint2* sB2 = (const uint2*)(smem + SM_B2) + cur * 2048;
        const uint4* sB3 = (const uint4*)(smem + SM_B3) + cur * 512;
        const uint4* sWB = (const uint4*)(smem + SM_WB) + cur * 256;
        const float* sM  = (const float*)(smem + SM_MISC) + cur * 128;
        const float* sB2v = sM;
        const float* sB3v = sM + 64;
        const float* sW4v = sM + 96;

        uint32_t xh[4];
        #pragma unroll
        for (int j = 0; j < 4; ++j) {
            float xx = __shfl_sync(0xffffffffu, xv, g + 8 * j);
            xh[j] = packh2(xx, xx);
        }

        // ---- layer 1 (f16x2 in fragment order) + layer 2 MMA, 1 pass ----
        float acc2[2][8][4] = {};
        #pragma unroll
        for (int half = 0; half < 2; ++half) {
            #pragma unroll
            for (int kt = 0; kt < 4; ++kt) {
                uint4 wb = sWB[(half * 4 + kt) * 32 + lam];
                uint32_t A[2][4];
                #pragma unroll
                for (int mt = 0; mt < 2; ++mt)
                    #pragma unroll
                    for (int i2 = 0; i2 < 2; ++i2) {
                        uint32_t xx = xh[mt * 2 + i2];
                        A[mt][i2]     = hfma2_relu(xx, wb.x, wb.z);
                        A[mt][i2 + 2] = hfma2_relu(xx, wb.y, wb.w);
                    }
                const uint2* bp = sB2 + ((half * 4 + kt) * 8) * 32;
                #pragma unroll
                for (int nt = 0; nt < 8; ++nt) {
                    uint2 B = bp[nt * 32 + lam];
                    #pragma unroll
                    for (int mt = 0; mt < 2; ++mt)
                        mma16816(acc2[mt][nt], A[mt], B.x, B.y);
                }
            }
        }

        // ---- epi2 + layer 3 fused per kt3 (A single, B split -> 2 passes) ----
        float acc3[2][4][4] = {};
        #pragma unroll
        for (int kt3 = 0; kt3 < 4; ++kt3) {
            uint32_t a3[2][4];
            #pragma unroll
            for (int mt = 0; mt < 2; ++mt)
                #pragma unroll
                for (int j = 0; j < 2; ++j) {
                    int nt = kt3 * 2 + j;
                    float2 bv = *(const float2*)(sB2v + nt * 8 + 2 * tig);
                    float v0 = fmaxf(acc2[mt][nt][0] + bv.x, 0.0f);
                    float v1 = fmaxf(acc2[mt][nt][1] + bv.y, 0.0f);
                    float v2 = fmaxf(acc2[mt][nt][2] + bv.x, 0.0f);
                    float v3 = fmaxf(acc2[mt][nt][3] + bv.y, 0.0f);
                    a3[mt][j * 2]     = packh2(v0, v1);
                    a3[mt][j * 2 + 1] = packh2(v2, v3);
                }
            const uint4* bp = sB3 + (kt3 * 4) * 32;
            #pragma unroll
            for (int nt = 0; nt < 4; ++nt) {
                uint4 B = bp[nt * 32 + lam];
                #pragma unroll
                for (int mt = 0; mt < 2; ++mt) {
                    mma16816(acc3[mt][nt], a3[mt], B.x, B.y);   // A*BH
                    mma16816(acc3[mt][nt], a3[mt], B.z, B.w);   // A*BL
                }
            }
        }

        // ---- epi3: +b3, relu, dot W4, warp reduce, write table value ----
        {
            float r0 = 0.f, r1 = 0.f, r2 = 0.f, r3 = 0.f;
            #pragma unroll
            for (int mt = 0; mt < 2; ++mt)
                #pragma unroll
                for (int nt = 0; nt < 4; ++nt) {
                    int col = nt * 8 + tig * 2;
                    float2 b3v = *(const float2*)(sB3v + col);
                    float2 w4v = *(const float2*)(sW4v + col);
                    float lo = fmaxf(acc3[mt][nt][0] + b3v.x, 0.f) * w4v.x
                             + fmaxf(acc3[mt][nt][1] + b3v.y, 0.f) * w4v.y;
                    float hi = fmaxf(acc3[mt][nt][2] + b3v.x, 0.f) * w4v.x
                             + fmaxf(acc3[mt][nt][3] + b3v.y, 0.f) * w4v.y;
                    if (mt == 0) { r0 += lo; r1 += hi; }
                    else         { r2 += lo; r3 += hi; }
                }
            #pragma unroll
            for (int d = 1; d <= 2; d <<= 1) {
                r0 += __shfl_xor_sync(0xffffffffu, r0, d);
                r1 += __shfl_xor_sync(0xffffffffu, r1, d);
                r2 += __shfl_xor_sync(0xffffffffu, r2, d);
                r3 += __shfl_xor_sync(0xffffffffu, r3, d);
            }
            int src = (lam & 7) * 4;
            float t0 = __shfl_sync(0xffffffffu, r0, src);
            float t1 = __shfl_sync(0xffffffffu, r1, src);
            float t2 = __shfl_sync(0xffffffffu, r2, src);
            float t3 = __shfl_sync(0xffffffffu, r3, src);
            int sel = lam >> 3;
            float fout = (sel == 0) ? t0 : (sel == 1) ? t1 : (sel == 2) ? t2 : t3;
            g_tabV[(size_t)f * TROWS + row] = fout + __ldg(b4 + f);
        }
    }
}

// ---------------------------------------------------------------------------
// eval: out[b] = bias + sum_f lerp(tabV_f, x[b,f]).
// 512 blocks x 256 threads; block = 16 rows x 16 feature-chunks (16 features
// per thread, fully unrolled -> deep MLP of independent L2 gathers).
// ---------------------------------------------------------------------------
__global__ __launch_bounds__(256)
void nam_eval(const float* __restrict__ x, const float* __restrict__ bias,
              float* __restrict__ out)
{
    __shared__ float sX[F_TOTAL * EV_STRIDE];      // [256 f][17] = 17 KB
    __shared__ float sred[16][16];
    const int tid = threadIdx.x;
    const int b0 = blockIdx.x * EV_ROWS;

    // coalesced load + smem transpose: 16 rows x 64 float4 = 1024, 4/thread
    #pragma unroll
    for (int i = 0; i < 4; ++i) {
        int idx4 = tid + i * 256;                  // float4 index
        int r = idx4 >> 6, c4 = idx4 & 63;
        float4 v = ((const float4*)(x + (size_t)(b0 + r) * F_TOTAL))[c4];
        int f = c4 * 4;
        sX[(f + 0) * EV_STRIDE + r] = v.x;
        sX[(f + 1) * EV_STRIDE + r] = v.y;
        sX[(f + 2) * EV_STRIDE + r] = v.z;
        sX[(f + 3) * EV_STRIDE + r] = v.w;
    }
    __syncthreads();

    const int rloc = tid & 15, chunk = tid >> 4;
    const int fb = chunk * 16;

    float a0 = 0.f, a1 = 0.f, a2 = 0.f, a3 = 0.f;
    #pragma unroll
    for (int j = 0; j < 16; j += 4) {
        #pragma unroll
        for (int q = 0; q < 4; ++q) {
            int f = fb + j + q;
            float xv = sX[f * EV_STRIDE + rloc];
            float u = fmaf(xv, T_IDEL, T_OFS);     // (x - T_LO) / Delta
            int i = __float2int_rd(u);
            i = min(max(i, 0), NB - 1);
            float frac = u - (float)i;
            const float* tp = g_tabV + (size_t)f * TROWS + i;
            float v0 = __ldg(tp);
            float v1 = __ldg(tp + 1);
            float y = fmaf(frac, v1 - v0, v0);
            if (q == 0) a0 += y; else if (q == 1) a1 += y;
            else if (q == 2) a2 += y; else a3 += y;
        }
    }
    sred[chunk][rloc] = (a0 + a1) + (a2 + a3);
    __syncthreads();
    if (tid < 16) {
        float s = bias[0];
        #pragma unroll
        for (int c = 0; c < 16; ++c)
            s += sred[c][tid];
        out[b0 + tid] = s;
    }
}

// ---------------------------------------------------------------------------
extern "C" void kernel_launch(void* const* d_in, const int* in_sizes, int n_in,
                              void* d_out, int out_size)
{
    (void)in_sizes; (void)n_in; (void)out_size;
    const float* x    = (const float*)d_in[0];
    const float* W1   = (const float*)d_in[1];
    const float* b1   = (const float*)d_in[2];
    const float* W2   = (const float*)d_in[3];
    const float* b2   = (const float*)d_in[4];
    const float* W3   = (const float*)d_in[5];
    const float* b3   = (const float*)d_in[6];
    const float* W4   = (const float*)d_in[7];
    const float* b4   = (const float*)d_in[8];
    const float* bias = (const float*)d_in[9];
    float* out = (float*)d_out;

    cudaFuncSetAttribute(nam_build, cudaFuncAttributeMaxDynamicSharedMemorySize,
                         SMEM_BYTES);

    prep_w<<<dim3(F_TOTAL, 2), 256>>>(W2, W3, W1, b1);
    nam_build<<<dim3(TBT, TFG), NTHREADS, SMEM_BYTES>>>(b2, b3, W4, b4);
    nam_eval<<<B_TOTAL / EV_ROWS, 256>>>(x, bias, out);
}

// round 15
// speedup vs baseline: 58.5596x; 1.0590x over previous
#include <cuda_runtime.h>
#include <cuda_fp16.h>
#include <cstdint>

// ---------------------------------------------------------------------------
// NAM via per-feature 1-D piecewise-linear tabulation (v4).
//   Build (fused): per (row-half, feature) block loads RAW weights once via
//   cp.async, converts to MMA fragment records in SMEM, then runs 3 row-tiles
//   of the f16 mma.sync pipeline. prep_w kernel eliminated.
//   Eval: out[b] = bias + sum_f lerp(tabV_f, x[b,f]).
// ---------------------------------------------------------------------------

#define B_TOTAL 8192
#define F_TOTAL 256

// table config (exact power-of-two grid)
#define NB      512
#define T_LO    (-8.0f)
#define T_IDEL  32.0f           // 1/Delta
#define T_DEL   0.03125f        // 2^-5
#define T_OFS   256.0f          // -T_LO * T_IDEL
#define TROWS   768             // 6 row-tiles of 128 (need 513 points)

// build smem layout (float/byte offsets from base)
#define SM_B2   0u              // 2048 uint2 = 16384 B
#define SM_B3   16384u          // 512 uint4 =  8192 B
#define SM_WB   24576u          // 256 uint4 =  4096 B
#define SM_MISC 28672u          // 128 float =   512 B
#define SM_RAW  29184u          // 10496 float = 41984 B
#define SMEM_BYTES 71168u
// raw area float offsets
#define RW2 0
#define RW3 8192
#define RW1 10240
#define RB1 10368

// eval config
#define EV_ROWS   16
#define EV_STRIDE 17

__device__ float g_tabV[F_TOTAL * TROWS];          // 768 KB

// ---- helpers ---------------------------------------------------------------
__device__ __forceinline__ uint32_t packh2(float v0, float v1) {
    uint32_t r;                     // low half = v0, high half = v1
    asm("cvt.rn.f16x2.f32 %0, %1, %2;" : "=r"(r) : "f"(v1), "f"(v0));
    return r;
}
__device__ __forceinline__ void splith2(float v0, float v1,
                                        uint32_t& hi, uint32_t& lo) {
    hi = packh2(v0, v1);
    __half2 h = *(__half2*)&hi;
    float2 r = __half22float2(h);
    lo = packh2(v0 - r.x, v1 - r.y);
}
__device__ __forceinline__ uint32_t hfma2_relu(uint32_t x, uint32_t w, uint32_t b) {
    uint32_t t;
    asm("fma.rn.f16x2 %0, %1, %2, %3;" : "=r"(t) : "r"(x), "r"(w), "r"(b));
    uint32_t z;
    asm("max.f16x2 %0, %1, %2;" : "=r"(z) : "r"(t), "r"(0u));
    return z;
}
__device__ __forceinline__ void mma16816(float* c, const uint32_t* a,
                                         uint32_t b0, uint32_t b1) {
    asm volatile(
        "mma.sync.aligned.m16n8k16.row.col.f32.f16.f16.f32 "
        "{%0,%1,%2,%3}, {%4,%5,%6,%7}, {%8,%9}, {%0,%1,%2,%3};"
        : "+f"(c[0]), "+f"(c[1]), "+f"(c[2]), "+f"(c[3])
        : "r"(a[0]), "r"(a[1]), "r"(a[2]), "r"(a[3]), "r"(b0), "r"(b1));
}
__device__ __forceinline__ void cp16(uint32_t dst, const void* src) {
    asm volatile("cp.async.cg.shared.global [%0], [%1], 16;"
                 :: "r"(dst), "l"(src));
}
#define CP_COMMIT() asm volatile("cp.async.commit_group;" ::: "memory")
#define CP_WAIT0()  asm volatile("cp.async.wait_group 0;" ::: "memory")

// ---------------------------------------------------------------------------
// build (fused conversion + MMA): grid (2 row-halves, 256 features), 128 thr.
// ---------------------------------------------------------------------------
__global__ __launch_bounds__(128)
void nam_build(const float* __restrict__ W1, const float* __restrict__ b1,
               const float* __restrict__ W2, const float* __restrict__ b2,
               const float* __restrict__ W3, const float* __restrict__ b3,
               const float* __restrict__ W4, const float* __restrict__ b4)
{
    extern __shared__ __align__(16) char smem[];
    const uint32_t sbase = (uint32_t)__cvta_generic_to_shared(smem);

    const int tid = threadIdx.x;
    const int lam = tid & 31;
    const int g = lam >> 2, tig = lam & 3;
    const int bx = blockIdx.x;            // row-half: tiles [3*bx, 3*bx+3)
    const int f  = blockIdx.y;

    float* raw = (float*)(smem + SM_RAW);
    uint2* sB2 = (uint2*)(smem + SM_B2);
    uint4* sB3 = (uint4*)(smem + SM_B3);
    uint4* sWB = (uint4*)(smem + SM_WB);
    float* sM  = (float*)(smem + SM_MISC);
    const float* sB2v = sM;
    const float* sB3v = sM + 64;
    const float* sW4v = sM + 96;

    // ---- phase A: cp.async raw weights into smem --------------------------
    {
        const uint32_t dr = sbase + SM_RAW;
        const char* w2p = (const char*)(W2 + (size_t)f * 8192);
        #pragma unroll
        for (int i = 0; i < 16; ++i) {
            int t = tid + i * 128;
            cp16(dr + RW2 * 4 + t * 16, w2p + t * 16);
        }
        const char* w3p = (const char*)(W3 + (size_t)f * 2048);
        #pragma unroll
        for (int i = 0; i < 4; ++i) {
            int t = tid + i * 128;
            cp16(dr + RW3 * 4 + t * 16, w3p + t * 16);
        }
        if (tid < 32)
            cp16(dr + RW1 * 4 + tid * 16, W1 + (size_t)f * 128 + tid * 4);
        else if (tid < 64)
            cp16(dr + RB1 * 4 + (tid - 32) * 16, b1 + (size_t)f * 128 + (tid - 32) * 4);
        else if (tid < 80)
            cp16(sbase + SM_MISC + (tid - 64) * 16, b2 + (size_t)f * 64 + (tid - 64) * 4);
        else if (tid < 88)
            cp16(sbase + SM_MISC + 256 + (tid - 80) * 16, b3 + (size_t)f * 32 + (tid - 80) * 4);
        else if (tid < 96)
            cp16(sbase + SM_MISC + 384 + (tid - 88) * 16, W4 + (size_t)f * 32 + (tid - 88) * 4);
        CP_COMMIT();
        CP_WAIT0();
        __syncthreads();
    }

    // ---- phase B: convert raw -> fragment records in smem ------------------
    {
        const float* s2 = raw + RW2;              // [128 k][64 n]
        #pragma unroll
        for (int i = 0; i < 16; ++i) {
            int e = tid + i * 128;
            int le = e & 31, nt = (e >> 5) & 7, kt = (e >> 8) & 3, hf = (e >> 10) & 1;
            int ge = le >> 2, te = le & 3;
            int n = nt * 8 + ge;
            int k0 = hf * 64 + kt * 16 + te * 2;
            uint32_t h0 = packh2(s2[k0 * 64 + n],       s2[(k0 + 1) * 64 + n]);
            uint32_t h1 = packh2(s2[(k0 + 8) * 64 + n], s2[(k0 + 9) * 64 + n]);
            sB2[e] = make_uint2(h0, h1);
        }
        const float* s3 = raw + RW3;              // [64 k][32 n]
        #pragma unroll
        for (int i = 0; i < 4; ++i) {
            int e = tid + i * 128;
            int le = e & 31, nt = (e >> 5) & 3, kt = (e >> 7) & 3;
            int ge = le >> 2, te = le & 3;
            int n = nt * 8 + ge;
            int k0 = kt * 16 + te * 2;
            uint32_t h0, l0, h1, l1;
            splith2(s3[k0 * 32 + n],       s3[(k0 + 1) * 32 + n], h0, l0);
            splith2(s3[(k0 + 8) * 32 + n], s3[(k0 + 9) * 32 + n], h1, l1);
            sB3[e] = make_uint4(h0, h1, l0, l1);
        }
        const float* w1 = raw + RW1;
        const float* bb1 = raw + RB1;
        #pragma unroll
        for (int i = 0; i < 2; ++i) {
            int e = tid + i * 128;
            int le = e & 31, kt = (e >> 5) & 3, hf = (e >> 7) & 1;
            int te = le & 3;
            int c = hf * 64 + kt * 16 + te * 2;
            sWB[e] = make_uint4(packh2(w1[c], w1[c + 1]), packh2(w1[c + 8], w1[c + 9]),
                                packh2(bb1[c], bb1[c + 1]), packh2(bb1[c + 8], bb1[c + 9]));
        }
        __syncthreads();
    }

    // ---- phase C: 3 row-tiles of the MMA pipeline --------------------------
    const float b4v = __ldg(b4 + f);

    #pragma unroll
    for (int t = 0; t < 3; ++t) {
        const int row = (bx * 3 + t) * 128 + tid;
        const float xv = T_LO + (float)row * T_DEL;   // exact grid point

        uint32_t xh[4];
        #pragma unroll
        for (int j = 0; j < 4; ++j) {
            float xx = __shfl_sync(0xffffffffu, xv, g + 8 * j);
            xh[j] = packh2(xx, xx);
        }

        // ---- layer 1 (f16x2 in fragment order) + layer 2 MMA, 1 pass ----
        float acc2[2][8][4] = {};
        #pragma unroll
        for (int half = 0; half < 2; ++half) {
            #pragma unroll
            for (int kt = 0; kt < 4; ++kt) {
                uint4 wb = sWB[(half * 4 + kt) * 32 + lam];
                uint32_t A[2][4];
                #pragma unroll
                for (int mt = 0; mt < 2; ++mt)
                    #pragma unroll
                    for (int i2 = 0; i2 < 2; ++i2) {
                        uint32_t xx = xh[mt * 2 + i2];
                        A[mt][i2]     = hfma2_relu(xx, wb.x, wb.z);
                        A[mt][i2 + 2] = hfma2_relu(xx, wb.y, wb.w);
                    }
                const uint2* bp = sB2 + ((half * 4 + kt) * 8) * 32;
                #pragma unroll
                for (int nt = 0; nt < 8; ++nt) {
                    uint2 B = bp[nt * 32 + lam];
                    #pragma unroll
                    for (int mt = 0; mt < 2; ++mt)
                        mma16816(acc2[mt][nt], A[mt], B.x, B.y);
                }
            }
        }

        // ---- epi2 + layer 3 fused per kt3 (A single, B split -> 2 passes) ----
        float acc3[2][4][4] = {};
        #pragma unroll
        for (int kt3 = 0; kt3 < 4; ++kt3) {
            uint32_t a3[2][4];
            #pragma unroll
            for (int mt = 0; mt < 2; ++mt)
                #pragma unroll
                for (int j = 0; j < 2; ++j) {
                    int nt = kt3 * 2 + j;
                    float2 bv = *(const float2*)(sB2v + nt * 8 + 2 * tig);
                    float v0 = fmaxf(acc2[mt][nt][0] + bv.x, 0.0f);
                    float v1 = fmaxf(acc2[mt][nt][1] + bv.y, 0.0f);
                    float v2 = fmaxf(acc2[mt][nt][2] + bv.x, 0.0f);
                    float v3 = fmaxf(acc2[mt][nt][3] + bv.y, 0.0f);
                    a3[mt][j * 2]     = packh2(v0, v1);
                    a3[mt][j * 2 + 1] = packh2(v2, v3);
                }
            const uint4* bp = sB3 + (kt3 * 4) * 32;
            #pragma unroll
            for (int nt = 0; nt < 4; ++nt) {
                uint4 B = bp[nt * 32 + lam];
                #pragma unroll
                for (int mt = 0; mt < 2; ++mt) {
                    mma16816(acc3[mt][nt], a3[mt], B.x, B.y);   // A*BH
                    mma16816(acc3[mt][nt], a3[mt], B.z, B.w);   // A*BL
                }
            }
        }

        // ---- epi3: +b3, relu, dot W4, warp reduce, write table value ----
        {
            float r0 = 0.f, r1 = 0.f, r2 = 0.f, r3 = 0.f;
            #pragma unroll
            for (int mt = 0; mt < 2; ++mt)
                #pragma unroll
                for (int nt = 0; nt < 4; ++nt) {
                    int col = nt * 8 + tig * 2;
                    float2 b3v = *(const float2*)(sB3v + col);
                    float2 w4v = *(const float2*)(sW4v + col);
                    float lo = fmaxf(acc3[mt][nt][0] + b3v.x, 0.f) * w4v.x
                             + fmaxf(acc3[mt][nt][1] + b3v.y, 0.f) * w4v.y;
                    float hi = fmaxf(acc3[mt][nt][2] + b3v.x, 0.f) * w4v.x
                             + fmaxf(acc3[mt][nt][3] + b3v.y, 0.f) * w4v.y;
                    if (mt == 0) { r0 += lo; r1 += hi; }
                    else         { r2 += lo; r3 += hi; }
                }
            #pragma unroll
            for (int d = 1; d <= 2; d <<= 1) {
                r0 += __shfl_xor_sync(0xffffffffu, r0, d);
                r1 += __shfl_xor_sync(0xffffffffu, r1, d);
                r2 += __shfl_xor_sync(0xffffffffu, r2, d);
                r3 += __shfl_xor_sync(0xffffffffu, r3, d);
            }
            int src = (lam & 7) * 4;
            float t0 = __shfl_sync(0xffffffffu, r0, src);
            float t1 = __shfl_sync(0xffffffffu, r1, src);
            float t2 = __shfl_sync(0xffffffffu, r2, src);
            float t3 = __shfl_sync(0xffffffffu, r3, src);
            int sel = lam >> 3;
            float fout = (sel == 0) ? t0 : (sel == 1) ? t1 : (sel == 2) ? t2 : t3;
            g_tabV[(size_t)f * TROWS + row] = fout + b4v;
        }
    }
}

// ---------------------------------------------------------------------------
// eval: out[b] = bias + sum_f lerp(tabV_f, x[b,f]).
// 512 blocks x 256 threads; block = 16 rows x 16 feature-chunks.
// ---------------------------------------------------------------------------
__global__ __launch_bounds__(256)
void nam_eval(const float* __restrict__ x, const float* __restrict__ bias,
              float* __restrict__ out)
{
    __shared__ float sX[F_TOTAL * EV_STRIDE];      // [256 f][17] = 17 KB
    __shared__ float sred[16][16];
    const int tid = threadIdx.x;
    const int b0 = blockIdx.x * EV_ROWS;

    // coalesced load + smem transpose: 16 rows x 64 float4 = 1024, 4/thread
    #pragma unroll
    for (int i = 0; i < 4; ++i) {
        int idx4 = tid + i * 256;                  // float4 index
        int r = idx4 >> 6, c4 = idx4 & 63;
        float4 v = ((const float4*)(x + (size_t)(b0 + r) * F_TOTAL))[c4];
        int f = c4 * 4;
        sX[(f + 0) * EV_STRIDE + r] = v.x;
        sX[(f + 1) * EV_STRIDE + r] = v.y;
        sX[(f + 2) * EV_STRIDE + r] = v.z;
        sX[(f + 3) * EV_STRIDE + r] = v.w;
    }
    __syncthreads();

    const int rloc = tid & 15, chunk = tid >> 4;
    const int fb = chunk * 16;

    float a0 = 0.f, a1 = 0.f, a2 = 0.f, a3 = 0.f;
    #pragma unroll
    for (int j = 0; j < 16; j += 4) {
        #pragma unroll
        for (int q = 0; q < 4; ++q) {
            int f = fb + j + q;
            float xv = sX[f * EV_STRIDE + rloc];
            float u = fmaf(xv, T_IDEL, T_OFS);     // (x - T_LO) / Delta
            int i = __float2int_rd(u);
            i = min(max(i, 0), NB - 1);
            float frac = u - (float)i;
            const float* tp = g_tabV + (size_t)f * TROWS + i;
            float v0 = __ldg(tp);
            float v1 = __ldg(tp + 1);
            float y = fmaf(frac, v1 - v0, v0);
            if (q == 0) a0 += y; else if (q == 1) a1 += y;
            else if (q == 2) a2 += y; else a3 += y;
        }
    }
    sred[chunk][rloc] = (a0 + a1) + (a2 + a3);
    __syncthreads();
    if (tid < 16) {
        float s = bias[0];
        #pragma unroll
        for (int c = 0; c < 16; ++c)
            s += sred[c][tid];
        out[b0 + tid] = s;
    }
}

// ---------------------------------------------------------------------------
extern "C" void kernel_launch(void* const* d_in, const int* in_sizes, int n_in,
                              void* d_out, int out_size)
{
    (void)in_sizes; (void)n_in; (void)out_size;
    const float* x    = (const float*)d_in[0];
    const float* W1   = (const float*)d_in[1];
    const float* b1   = (const float*)d_in[2];
    const float* W2   = (const float*)d_in[3];
    const float* b2   = (const float*)d_in[4];
    const float* W3   = (const float*)d_in[5];
    const float* b3   = (const float*)d_in[6];
    const float* W4   = (const float*)d_in[7];
    const float* b4   = (const float*)d_in[8];
    const float* bias = (const float*)d_in[9];
    float* out = (float*)d_out;

    cudaFuncSetAttribute(nam_build, cudaFuncAttributeMaxDynamicSharedMemorySize,
                         SMEM_BYTES);

    nam_build<<<dim3(2, F_TOTAL), 128, SMEM_BYTES>>>(W1, b1, W2, b2, W3, b3, W4, b4);
    nam_eval<<<B_TOTAL / EV_ROWS, 256>>>(x, bias, out);
}